// round 15
// baseline (speedup 1.0000x reference)
#include <cuda_runtime.h>
#include <cuda_fp16.h>
#include <math.h>

#define NN 100000
#define NE 1600000
#define EMBD 64
#define EPSBN 1e-5f
#define NTILE (NE / 64)          // 25000
#define SCANB 98                 // ceil(NN/1024)

// ---------------- scratch (static device globals; no allocation) ----------------
__device__ __align__(16) float g_p[(size_t)NN * EMBD];
__device__ __align__(16) float g_q[(size_t)NN * EMBD];
__device__ __align__(16) float g_aggr[(size_t)NN * EMBD];
__device__ __align__(16) __half g_y2h[(size_t)NE * EMBD];   // 204.8 MB (fp16, dst-sorted edge order)
__device__ __align__(16) float g_y3[(size_t)NN * EMBD];
__device__ __align__(16) float g_y4[(size_t)NN * EMBD];
__device__ __align__(16) float4 g_x[NN];   // packed node features (pos.xy, vel.xy), 1.6 MB
__device__ int g_src[NE];
__device__ int g_dst[NE];
__device__ __align__(8) int2 g_se[NE];   // sorted edges: .x = dst, .y = src
__device__ int g_cnt[NN];         // indeg
__device__ int g_outc[NN];        // outdeg
__device__ int g_off[NN + 1];
__device__ int g_cur[NN];
__device__ int g_bsum[SCANB];
__device__ int g_bpre[SCANB];
__device__ float g_Cp[4 * EMBD];
__device__ float g_Cq[4 * EMBD];
__device__ float g_Cu[4 * EMBD];
__device__ float g_cb1[EMBD];
__device__ float g_cbu[EMBD];
__device__ float g_stats[8 * EMBD];
__device__ float g_bn[8 * EMBD];
// moments: [0:16) Mds, [16:32) Mdd, [32:48) Mss, [48:52) vd, [52:56) vs
__device__ float g_mom[56];
__device__ int g_is64;

__device__ __forceinline__ unsigned smem_u32(const void* p) {
    return (unsigned)__cvta_generic_to_shared(p);
}

// ---------------- init: zero cnt/outc/stats/mom; block 0 also detects int64 vs int32 ----------------
__global__ void k_init(const unsigned int* w) {
    int i = blockIdx.x * blockDim.x + threadIdx.x;
    if (i < NN) { g_cnt[i] = 0; g_outc[i] = 0; }
    if (blockIdx.x < 2) g_stats[blockIdx.x * 256 + threadIdx.x] = 0.f;
    if (blockIdx.x == 2 && threadIdx.x < 56) g_mom[threadIdx.x] = 0.f;
    if (blockIdx.x == 0) {
        __shared__ int bad;
        if (threadIdx.x == 0) bad = 0;
        __syncthreads();
        for (int k = 1 + 2 * threadIdx.x; k < 4096; k += 2 * blockDim.x)
            if (w[k] != 0u) bad = 1;
        __syncthreads();
        if (threadIdx.x == 0) g_is64 = bad ? 0 : 1;
    }
}

// ---------------- convert indices + dst/src histograms (fused) ----------------
__global__ void k_conv(const void* ei) {
    int e = blockIdx.x * blockDim.x + threadIdx.x;
    if (e >= NE) return;
    int s, d;
    if (g_is64) {
        const long long* p = (const long long*)ei;
        s = (int)p[e];
        d = (int)p[(size_t)NE + e];
    } else {
        const int* p = (const int*)ei;
        s = p[e];
        d = p[NE + e];
    }
    g_src[e] = s;
    g_dst[e] = d;
    atomicAdd(&g_cnt[d], 1);
    atomicAdd(&g_outc[s], 1);
}

// ---------------- 3-phase parallel exclusive scan ----------------
__global__ void k_scanA() {
    __shared__ int wsum[8];
    int b = blockIdx.x, t = threadIdx.x;
    int base = b * 1024;
    int s = 0;
    for (int i = t; i < 1024; i += 256) {
        int idx = base + i;
        s += (idx < NN) ? g_cnt[idx] : 0;
    }
#pragma unroll
    for (int o = 16; o; o >>= 1) s += __shfl_down_sync(0xffffffffu, s, o);
    if ((t & 31) == 0) wsum[t >> 5] = s;
    __syncthreads();
    if (t == 0) {
        int tot = 0;
#pragma unroll
        for (int i = 0; i < 8; i++) tot += wsum[i];
        g_bsum[b] = tot;
    }
}

__global__ void k_scanB() {
    __shared__ int sh[SCANB];
    int t = threadIdx.x;
    if (t < SCANB) sh[t] = g_bsum[t];
    __syncthreads();
    if (t == 0) {
        int run = 0;
        for (int i = 0; i < SCANB; i++) { int c = sh[i]; sh[i] = run; run += c; }
    }
    __syncthreads();
    if (t < SCANB) g_bpre[t] = sh[t];
}

__global__ void k_scanC() {
    __shared__ int ws[32];
    int b = blockIdx.x, t = threadIdx.x;
    int idx = b * 1024 + t;
    int v = (idx < NN) ? g_cnt[idx] : 0;
    int lane = t & 31, w = t >> 5;
    int incl = v;
#pragma unroll
    for (int o = 1; o < 32; o <<= 1) { int u = __shfl_up_sync(0xffffffffu, incl, o); if (lane >= o) incl += u; }
    if (lane == 31) ws[w] = incl;
    __syncthreads();
    if (w == 0) {
        int x = ws[lane];
#pragma unroll
        for (int o = 1; o < 32; o <<= 1) { int u = __shfl_up_sync(0xffffffffu, x, o); if (lane >= o) x += u; }
        ws[lane] = x;
    }
    __syncthreads();
    int excl = incl - v + (w > 0 ? ws[w - 1] : 0) + g_bpre[b];
    if (idx < NN) { g_off[idx] = excl; g_cur[idx] = excl; }
    if (idx == 0) g_off[NN] = NE;
}

__global__ void k_scatter() {
    int e = blockIdx.x * blockDim.x + threadIdx.x;
    if (e >= NE) return;
    int d = g_dst[e];
    int pos = atomicAdd(&g_cur[d], 1);
    g_se[pos] = make_int2(d, g_src[e]);
}

// ---------------- composite 4x64 matrices (3 concurrent blocks) ----------------
__global__ void k_pre(const float* W_in, const float* b_in,
                      const float* mW1, const float* mb1,
                      const float* uW1, const float* ub1) {
    int tid = threadIdx.x;
    int f = tid >> 6, c = tid & 63;
    int m = blockIdx.x;
    const float* W = (m == 0) ? mW1 : (m == 1) ? (mW1 + 64 * EMBD) : uW1;
    float s = 0.f;
#pragma unroll 8
    for (int k = 0; k < EMBD; k++) s += W_in[f * EMBD + k] * W[k * EMBD + c];
    float* C = (m == 0) ? g_Cp : (m == 1) ? g_Cq : g_Cu;
    C[tid] = s;
    if (f == 0) {
        if (m == 0) {
            float s1 = mb1[c];
#pragma unroll 8
            for (int k = 0; k < EMBD; k++)
                s1 += b_in[k] * (mW1[k * EMBD + c] + mW1[(EMBD + k) * EMBD + c]);
            g_cb1[c] = s1;
        } else if (m == 2) {
            float s2 = ub1[c];
#pragma unroll 8
            for (int k = 0; k < EMBD; k++) s2 += b_in[k] * uW1[k * EMBD + c];
            g_cbu[c] = s2;
        }
    }
}

// ---------------- per-node p,q + packed features ----------------
__global__ void k_pq(const float* pos, const float* vel) {
    int i = blockIdx.x * blockDim.x + threadIdx.x;
    if (i >= NN * EMBD) return;
    int n = i >> 6, c = i & 63;
    float x0 = pos[2 * n], x1 = pos[2 * n + 1];
    float x2 = vel[2 * n], x3 = vel[2 * n + 1];
    g_p[i] = x0 * g_Cp[c] + x1 * g_Cp[64 + c] + x2 * g_Cp[128 + c] + x3 * g_Cp[192 + c];
    g_q[i] = x0 * g_Cq[c] + x1 * g_Cq[64 + c] + x2 * g_Cq[128 + c] + x3 * g_Cq[192 + c];
    if (c == 0) g_x[n] = make_float4(x0, x1, x2, x3);
}

// ---------------- edge moment pass: Mds[i][j] = sum_e x_dst[i]*x_src[j] ----------------
__global__ void __launch_bounds__(256) k_momE() {
    float m[16];
#pragma unroll
    for (int k = 0; k < 16; k++) m[k] = 0.f;
    int stride = gridDim.x * blockDim.x;
    for (int e = blockIdx.x * blockDim.x + threadIdx.x; e < NE; e += stride) {
        float4 xd = g_x[g_dst[e]];
        float4 xs = g_x[g_src[e]];
        const float* a = &xd.x;
        const float* b = &xs.x;
#pragma unroll
        for (int i = 0; i < 4; i++)
#pragma unroll
            for (int j = 0; j < 4; j++)
                m[i * 4 + j] = fmaf(a[i], b[j], m[i * 4 + j]);
    }
    __shared__ float sh[8][16];
    int lane = threadIdx.x & 31, w = threadIdx.x >> 5;
#pragma unroll
    for (int k = 0; k < 16; k++) {
#pragma unroll
        for (int o = 16; o; o >>= 1) m[k] += __shfl_down_sync(0xffffffffu, m[k], o);
    }
    if (lane == 0) {
#pragma unroll
        for (int k = 0; k < 16; k++) sh[w][k] = m[k];
    }
    __syncthreads();
    if (w == 0 && lane < 16) {
        float t = 0.f;
#pragma unroll
        for (int y = 0; y < 8; y++) t += sh[y][lane];
        atomicAdd(&g_mom[lane], t);
    }
}

// ---------------- node moment pass: Mdd, Mss, vd, vs (degree-weighted) ----------------
__global__ void __launch_bounds__(256) k_momN() {
    float mdd[16], mss[16], vd[4], vs[4];
#pragma unroll
    for (int k = 0; k < 16; k++) { mdd[k] = 0.f; mss[k] = 0.f; }
#pragma unroll
    for (int k = 0; k < 4; k++) { vd[k] = 0.f; vs[k] = 0.f; }
    int stride = gridDim.x * blockDim.x;
    for (int n = blockIdx.x * blockDim.x + threadIdx.x; n < NN; n += stride) {
        float4 x = g_x[n];
        const float* a = &x.x;
        float wi = (float)g_cnt[n], wo = (float)g_outc[n];
#pragma unroll
        for (int i = 0; i < 4; i++) {
            vd[i] = fmaf(wi, a[i], vd[i]);
            vs[i] = fmaf(wo, a[i], vs[i]);
#pragma unroll
            for (int j = 0; j < 4; j++) {
                float pij = a[i] * a[j];
                mdd[i * 4 + j] = fmaf(wi, pij, mdd[i * 4 + j]);
                mss[i * 4 + j] = fmaf(wo, pij, mss[i * 4 + j]);
            }
        }
    }
    __shared__ float sh[8][40];
    int lane = threadIdx.x & 31, w = threadIdx.x >> 5;
#pragma unroll
    for (int k = 0; k < 16; k++) {
#pragma unroll
        for (int o = 16; o; o >>= 1) {
            mdd[k] += __shfl_down_sync(0xffffffffu, mdd[k], o);
            mss[k] += __shfl_down_sync(0xffffffffu, mss[k], o);
        }
    }
#pragma unroll
    for (int k = 0; k < 4; k++) {
#pragma unroll
        for (int o = 16; o; o >>= 1) {
            vd[k] += __shfl_down_sync(0xffffffffu, vd[k], o);
            vs[k] += __shfl_down_sync(0xffffffffu, vs[k], o);
        }
    }
    if (lane == 0) {
#pragma unroll
        for (int k = 0; k < 16; k++) { sh[w][k] = mdd[k]; sh[w][16 + k] = mss[k]; }
#pragma unroll
        for (int k = 0; k < 4; k++) { sh[w][32 + k] = vd[k]; sh[w][36 + k] = vs[k]; }
    }
    __syncthreads();
    if (w == 0 && lane < 32) {
        // entries 0..39 map to g_mom[16..55]
        if (lane < 32) {
            float t = 0.f;
#pragma unroll
            for (int y = 0; y < 8; y++) t += sh[y][lane];
            atomicAdd(&g_mom[16 + lane], t);
        }
    }
    __syncthreads();
    if (w == 1 && lane < 8) {
        float t = 0.f;
#pragma unroll
        for (int y = 0; y < 8; y++) t += sh[y][32 + lane];
        atomicAdd(&g_mom[48 + lane], t);
    }
}

// ---------------- BN1 coefficients from moments ----------------
__global__ void k_bnmom(const float* gamma, const float* beta) {
    __shared__ float mom[56];
    int c = threadIdx.x;
    if (c < 56) mom[c] = g_mom[c];
    __syncthreads();
    float Cp[4], Cq[4];
#pragma unroll
    for (int i = 0; i < 4; i++) { Cp[i] = g_Cp[i * 64 + c]; Cq[i] = g_Cq[i * 64 + c]; }
    float cb = g_cb1[c];
    float sp = 0.f, sq = 0.f;
#pragma unroll
    for (int i = 0; i < 4; i++) { sp += mom[48 + i] * Cp[i]; sq += mom[52 + i] * Cq[i]; }
    float S1 = sp + sq + (float)NE * cb;
    float q2 = 0.f;
#pragma unroll
    for (int i = 0; i < 4; i++)
#pragma unroll
        for (int j = 0; j < 4; j++) {
            q2 += Cp[i] * Cp[j] * mom[16 + i * 4 + j];
            q2 += Cq[i] * Cq[j] * mom[32 + i * 4 + j];
            q2 += 2.f * Cp[i] * Cq[j] * mom[i * 4 + j];
        }
    float S2 = q2 + 2.f * cb * (sp + sq) + (float)NE * cb * cb;
    float mu = S1 / (float)NE;
    float var = S2 / (float)NE - mu * mu;
    float a = gamma[c] * rsqrtf(fmaxf(var, 0.f) + EPSBN);
    g_bn[c] = a;
    g_bn[64 + c] = beta[c] - mu * a;
}

// ---------------- fold BN stats into per-channel (a, s) — layers 1..3 ----------------
__global__ void k_bn(int layer, float cnt, const float* gamma, const float* beta) {
    int c = threadIdx.x;
    float mu = g_stats[layer * 128 + c] / cnt;
    float v  = g_stats[layer * 128 + 64 + c] / cnt - mu * mu;
    float a  = gamma[c] * rsqrtf(fmaxf(v, 0.f) + EPSBN);
    g_bn[layer * 128 + c] = a;
    g_bn[layer * 128 + 64 + c] = beta[c] - mu * a;
}

// ---------------- scalar 64x64 register-blocked GEMM core (node kernels) ----------------
__device__ __forceinline__ void tile_gemm(const float (*zs)[68], const float (*sw)[64],
                                          int r0, int c0, float acc[4][4]) {
#pragma unroll
    for (int k = 0; k < 64; k += 4) {
        float4 A0 = *(const float4*)&zs[r0 + 0][k];
        float4 A1 = *(const float4*)&zs[r0 + 1][k];
        float4 A2 = *(const float4*)&zs[r0 + 2][k];
        float4 A3 = *(const float4*)&zs[r0 + 3][k];
        const float* a0 = (const float*)&A0;
        const float* a1 = (const float*)&A1;
        const float* a2 = (const float*)&A2;
        const float* a3 = (const float*)&A3;
#pragma unroll
        for (int kk = 0; kk < 4; kk++) {
            float4 B = *(const float4*)&sw[k + kk][c0];
            acc[0][0] = fmaf(a0[kk], B.x, acc[0][0]);
            acc[0][1] = fmaf(a0[kk], B.y, acc[0][1]);
            acc[0][2] = fmaf(a0[kk], B.z, acc[0][2]);
            acc[0][3] = fmaf(a0[kk], B.w, acc[0][3]);
            acc[1][0] = fmaf(a1[kk], B.x, acc[1][0]);
            acc[1][1] = fmaf(a1[kk], B.y, acc[1][1]);
            acc[1][2] = fmaf(a1[kk], B.z, acc[1][2]);
            acc[1][3] = fmaf(a1[kk], B.w, acc[1][3]);
            acc[2][0] = fmaf(a2[kk], B.x, acc[2][0]);
            acc[2][1] = fmaf(a2[kk], B.y, acc[2][1]);
            acc[2][2] = fmaf(a2[kk], B.z, acc[2][2]);
            acc[2][3] = fmaf(a2[kk], B.w, acc[2][3]);
            acc[3][0] = fmaf(a3[kk], B.x, acc[3][0]);
            acc[3][1] = fmaf(a3[kk], B.y, acc[3][1]);
            acc[3][2] = fmaf(a3[kk], B.z, acc[3][2]);
            acc[3][3] = fmaf(a3[kk], B.w, acc[3][3]);
        }
    }
}

__device__ __forceinline__ void tile_stats(float red[16][64], int ty, int c0,
                                           const float cs[4], const float cq[4],
                                           float* gsum, float* gsq) {
    int tid = threadIdx.x;
#pragma unroll
    for (int j = 0; j < 4; j++) red[ty][c0 + j] = cs[j];
    __syncthreads();
    if (tid < 64) {
        float t = 0.f;
#pragma unroll
        for (int y = 0; y < 16; y++) t += red[y][tid];
        atomicAdd(&gsum[tid], t);
    }
    __syncthreads();
#pragma unroll
    for (int j = 0; j < 4; j++) red[ty][c0 + j] = cq[j];
    __syncthreads();
    if (tid < 64) {
        float t = 0.f;
#pragma unroll
        for (int y = 0; y < 16; y++) t += red[y][tid];
        atomicAdd(&gsq[tid], t);
    }
}

// ---------------- edge layer 2: PERSISTENT tensor-core GEMM, double-buffered pipeline ----------------
__global__ void __launch_bounds__(256, 3) k_e2(const float* mW2, const float* mb2) {
    __shared__ __align__(16) __half zh[2][64][72];
    __shared__ __align__(16) __half wh[64][72];
    __shared__ float red[32][64];
    int tid = threadIdx.x;
#pragma unroll
    for (int i = 0; i < 16; i++) {
        int idx = i * 256 + tid;
        wh[idx >> 6][idx & 63] = __float2half(mW2[idx]);
    }
    int w = tid >> 5, lane = tid & 31;
    int m0 = (w & 3) * 16, n0b = (w >> 2) * 32;
    int grp = lane >> 3, li = lane & 7;
    int arow = m0 + li + (grp & 1) * 8;
    int akoff = (grp >> 1) * 8;
    unsigned zbase0 = smem_u32(&zh[0][0][0]);
    unsigned wbase = smem_u32(&wh[0][0]);
    const unsigned ZBUF = 64 * 72 * 2;
    int cg4 = (tid & 15) * 4;
    int rl = tid >> 4;
    float4 bn_cb = *(const float4*)&g_cb1[cg4];
    float4 bn_a  = *(const float4*)&g_bn[cg4];
    float4 bn_s  = *(const float4*)&g_bn[64 + cg4];
    float bias0[4][2];
#pragma unroll
    for (int q = 0; q < 4; q++) {
        int c = n0b + q * 8 + (lane & 3) * 2;
        bias0[q][0] = mb2[c]; bias0[q][1] = mb2[c + 1];
    }
    int r0s = m0 + (lane >> 2), r1s = r0s + 8;
    float scs[4][2] = {{0.f,0.f},{0.f,0.f},{0.f,0.f},{0.f,0.f}};
    float scq[4][2] = {{0.f,0.f},{0.f,0.f},{0.f,0.f},{0.f,0.f}};

    {
        int e0 = blockIdx.x * 64;
#pragma unroll
        for (int j = 0; j < 4; j++) {
            int r = rl + 16 * j;
            int2 v = g_se[e0 + r];
            float4 pp = *(const float4*)&g_p[(size_t)v.x * EMBD + cg4];
            float4 qq = *(const float4*)&g_q[(size_t)v.y * EMBD + cg4];
            __half2 h0 = __floats2half2_rn(
                fmaxf(fmaf(pp.x + qq.x + bn_cb.x, bn_a.x, bn_s.x), 0.f),
                fmaxf(fmaf(pp.y + qq.y + bn_cb.y, bn_a.y, bn_s.y), 0.f));
            __half2 h1 = __floats2half2_rn(
                fmaxf(fmaf(pp.z + qq.z + bn_cb.z, bn_a.z, bn_s.z), 0.f),
                fmaxf(fmaf(pp.w + qq.w + bn_cb.w, bn_a.w, bn_s.w), 0.f));
            uint2 u; u.x = *(unsigned*)&h0; u.y = *(unsigned*)&h1;
            *(uint2*)&zh[0][r][cg4] = u;
        }
    }
    __syncthreads();

    int buf = 0;
    for (int tile = blockIdx.x; tile < NTILE; tile += gridDim.x) {
        int e0 = tile * 64;
        int nxt = tile + gridDim.x;
        if (nxt < NTILE) {
            int f0 = nxt * 64;
#pragma unroll
            for (int j = 0; j < 4; j++) {
                int r = rl + 16 * j;
                int2 v = g_se[f0 + r];
                float4 pp = *(const float4*)&g_p[(size_t)v.x * EMBD + cg4];
                float4 qq = *(const float4*)&g_q[(size_t)v.y * EMBD + cg4];
                __half2 h0 = __floats2half2_rn(
                    fmaxf(fmaf(pp.x + qq.x + bn_cb.x, bn_a.x, bn_s.x), 0.f),
                    fmaxf(fmaf(pp.y + qq.y + bn_cb.y, bn_a.y, bn_s.y), 0.f));
                __half2 h1 = __floats2half2_rn(
                    fmaxf(fmaf(pp.z + qq.z + bn_cb.z, bn_a.z, bn_s.z), 0.f),
                    fmaxf(fmaf(pp.w + qq.w + bn_cb.w, bn_a.w, bn_s.w), 0.f));
                uint2 u; u.x = *(unsigned*)&h0; u.y = *(unsigned*)&h1;
                *(uint2*)&zh[buf ^ 1][r][cg4] = u;
            }
        }
        unsigned zb = zbase0 + (unsigned)buf * ZBUF;
        float acc[4][4];
#pragma unroll
        for (int q = 0; q < 4; q++) {
            acc[q][0] = bias0[q][0]; acc[q][1] = bias0[q][1];
            acc[q][2] = bias0[q][0]; acc[q][3] = bias0[q][1];
        }
#pragma unroll
        for (int ks = 0; ks < 4; ks++) {
            int k0 = ks * 16;
            unsigned a0, a1, a2, a3;
            unsigned aaddr = zb + (unsigned)(arow * 144 + (k0 + akoff) * 2);
            asm volatile("ldmatrix.sync.aligned.m8n8.x4.shared.b16 {%0,%1,%2,%3}, [%4];"
                         : "=r"(a0), "=r"(a1), "=r"(a2), "=r"(a3) : "r"(aaddr));
#pragma unroll
            for (int q = 0; q < 4; q++) {
                int n0 = n0b + q * 8;
                unsigned baddr = wbase + (unsigned)((k0 + (lane & 15)) * 144 + n0 * 2);
                unsigned b0, b1;
                asm volatile("ldmatrix.sync.aligned.m8n8.x2.trans.shared.b16 {%0,%1}, [%2];"
                             : "=r"(b0), "=r"(b1) : "r"(baddr));
                asm volatile("mma.sync.aligned.m16n8k16.row.col.f32.f16.f16.f32 "
                             "{%0,%1,%2,%3}, {%4,%5,%6,%7}, {%8,%9}, {%0,%1,%2,%3};"
                             : "+f"(acc[q][0]), "+f"(acc[q][1]), "+f"(acc[q][2]), "+f"(acc[q][3])
                             : "r"(a0), "r"(a1), "r"(a2), "r"(a3), "r"(b0), "r"(b1));
            }
        }
#pragma unroll
        for (int q = 0; q < 4; q++) {
            int c = n0b + q * 8 + (lane & 3) * 2;
            // streaming stores: keep the 205 MB y2 stream out of L2's hot set
            __stcs((__half2*)&g_y2h[(size_t)(e0 + r0s) * EMBD + c], __floats2half2_rn(acc[q][0], acc[q][1]));
            __stcs((__half2*)&g_y2h[(size_t)(e0 + r1s) * EMBD + c], __floats2half2_rn(acc[q][2], acc[q][3]));
            scs[q][0] += acc[q][0] + acc[q][2];
            scs[q][1] += acc[q][1] + acc[q][3];
            scq[q][0] += acc[q][0] * acc[q][0] + acc[q][2] * acc[q][2];
            scq[q][1] += acc[q][1] * acc[q][1] + acc[q][3] * acc[q][3];
        }
        __syncthreads();
        buf ^= 1;
    }

    int ridx = (w & 3) * 8 + (lane >> 2);
#pragma unroll
    for (int q = 0; q < 4; q++) {
        int c = n0b + q * 8 + (lane & 3) * 2;
        red[ridx][c] = scs[q][0]; red[ridx][c + 1] = scs[q][1];
    }
    __syncthreads();
    if (tid < 64) {
        float t = 0.f;
#pragma unroll
        for (int y = 0; y < 32; y++) t += red[y][tid];
        atomicAdd(&g_stats[128 + tid], t);
    }
    __syncthreads();
#pragma unroll
    for (int q = 0; q < 4; q++) {
        int c = n0b + q * 8 + (lane & 3) * 2;
        red[ridx][c] = scq[q][0]; red[ridx][c + 1] = scq[q][1];
    }
    __syncthreads();
    if (tid < 64) {
        float t = 0.f;
#pragma unroll
        for (int y = 0; y < 32; y++) t += red[y][tid];
        atomicAdd(&g_stats[192 + tid], t);
    }
}

// ---------------- segment-sum aggregation (NO atomics, streaming reads) ----------------
__global__ void __launch_bounds__(256) k_e3() {
    int gid = blockIdx.x * blockDim.x + threadIdx.x;
    int n = gid >> 3;
    if (n >= NN) return;
    int c = (gid & 7) * 8;
    float4 ba0 = *(const float4*)&g_bn[128 + c];
    float4 ba1 = *(const float4*)&g_bn[128 + c + 4];
    float4 bs0 = *(const float4*)&g_bn[192 + c];
    float4 bs1 = *(const float4*)&g_bn[192 + c + 4];
    int t0 = g_off[n], t1 = g_off[n + 1];
    float a0 = 0.f, a1 = 0.f, a2 = 0.f, a3 = 0.f, a4 = 0.f, a5 = 0.f, a6 = 0.f, a7 = 0.f;
    for (int t = t0; t < t1; t++) {
        uint4 raw = __ldcs((const uint4*)&g_y2h[((size_t)t << 6) + c]);
        float2 f0 = __half22float2(*(__half2*)&raw.x);
        float2 f1 = __half22float2(*(__half2*)&raw.y);
        float2 f2 = __half22float2(*(__half2*)&raw.z);
        float2 f3 = __half22float2(*(__half2*)&raw.w);
        a0 += fmaxf(fmaf(f0.x, ba0.x, bs0.x), 0.f);
        a1 += fmaxf(fmaf(f0.y, ba0.y, bs0.y), 0.f);
        a2 += fmaxf(fmaf(f1.x, ba0.z, bs0.z), 0.f);
        a3 += fmaxf(fmaf(f1.y, ba0.w, bs0.w), 0.f);
        a4 += fmaxf(fmaf(f2.x, ba1.x, bs1.x), 0.f);
        a5 += fmaxf(fmaf(f2.y, ba1.y, bs1.y), 0.f);
        a6 += fmaxf(fmaf(f3.x, ba1.z, bs1.z), 0.f);
        a7 += fmaxf(fmaf(f3.y, ba1.w, bs1.w), 0.f);
    }
    float* dp = &g_aggr[(size_t)n * EMBD + c];
    *(float4*)dp       = make_float4(a0, a1, a2, a3);
    *(float4*)(dp + 4) = make_float4(a4, a5, a6, a7);
}

// ---------------- node layer 1 ----------------
__global__ void __launch_bounds__(256) k_u1(const float* pos, const float* vel, const float* uW1) {
    __shared__ __align__(16) float as_[64][68];
    __shared__ __align__(16) float sw[64][64];
    __shared__ float red[16][64];
    __shared__ float sx[64][4];
    int tid = threadIdx.x;
    int n0 = blockIdx.x * 64;
#pragma unroll
    for (int i = 0; i < 16; i++) { int idx = i * 256 + tid; sw[idx >> 6][idx & 63] = uW1[4096 + idx]; }
    if (tid < 64) {
        int n = n0 + tid;
        if (n < NN) {
            sx[tid][0] = pos[2 * n]; sx[tid][1] = pos[2 * n + 1];
            sx[tid][2] = vel[2 * n]; sx[tid][3] = vel[2 * n + 1];
        } else {
            sx[tid][0] = sx[tid][1] = sx[tid][2] = sx[tid][3] = 0.f;
        }
    }
    {
        int c = tid & 63, l = tid >> 6;
#pragma unroll
        for (int j = 0; j < 16; j++) {
            int r = l + 4 * j; int n = n0 + r;
            as_[r][c] = (n < NN) ? g_aggr[(size_t)n * EMBD + c] : 0.f;
        }
    }
    __syncthreads();
    int tx = tid & 15, ty = tid >> 4;
    int c0 = tx * 4, r0 = ty * 4;
    float acc[4][4];
#pragma unroll
    for (int i = 0; i < 4; i++) {
        int r = r0 + i;
#pragma unroll
        for (int j = 0; j < 4; j++) {
            int c = c0 + j;
            acc[i][j] = g_cbu[c] + sx[r][0] * g_Cu[c] + sx[r][1] * g_Cu[64 + c]
                      + sx[r][2] * g_Cu[128 + c] + sx[r][3] * g_Cu[192 + c];
        }
    }
    tile_gemm(as_, sw, r0, c0, acc);
    float cs[4] = {0, 0, 0, 0}, cq[4] = {0, 0, 0, 0};
#pragma unroll
    for (int i = 0; i < 4; i++) {
        int n = n0 + r0 + i;
        if (n < NN) {
            float4 o; o.x = acc[i][0]; o.y = acc[i][1]; o.z = acc[i][2]; o.w = acc[i][3];
            *(float4*)&g_y3[(size_t)n * EMBD + c0] = o;
#pragma unroll
            for (int j = 0; j < 4; j++) { cs[j] += acc[i][j]; cq[j] += acc[i][j] * acc[i][j]; }
        }
    }
    tile_stats(red, ty, c0, cs, cq, &g_stats[256], &g_stats[320]);
}

// ---------------- node layer 2 ----------------
__global__ void __launch_bounds__(256) k_u2(const float* uW2, const float* ub2) {
    __shared__ __align__(16) float as_[64][68];
    __shared__ __align__(16) float sw[64][64];
    __shared__ float red[16][64];
    int tid = threadIdx.x;
    int n0 = blockIdx.x * 64;
#pragma unroll
    for (int i = 0; i < 16; i++) { int idx = i * 256 + tid; sw[idx >> 6][idx & 63] = uW2[idx]; }
    {
        int c = tid & 63, l = tid >> 6;
        float a3 = g_bn[256 + c], s3 = g_bn[320 + c];
#pragma unroll
        for (int j = 0; j < 16; j++) {
            int r = l + 4 * j; int n = n0 + r;
            as_[r][c] = (n < NN) ? fmaxf(fmaf(g_y3[(size_t)n * EMBD + c], a3, s3), 0.f) : 0.f;
        }
    }
    __syncthreads();
    int tx = tid & 15, ty = tid >> 4;
    int c0 = tx * 4, r0 = ty * 4;
    float acc[4][4];
#pragma unroll
    for (int j = 0; j < 4; j++) {
        float b = ub2[c0 + j];
        acc[0][j] = b; acc[1][j] = b; acc[2][j] = b; acc[3][j] = b;
    }
    tile_gemm(as_, sw, r0, c0, acc);
    float cs[4] = {0, 0, 0, 0}, cq[4] = {0, 0, 0, 0};
#pragma unroll
    for (int i = 0; i < 4; i++) {
        int n = n0 + r0 + i;
        if (n < NN) {
            float4 o; o.x = acc[i][0]; o.y = acc[i][1]; o.z = acc[i][2]; o.w = acc[i][3];
            *(float4*)&g_y4[(size_t)n * EMBD + c0] = o;
#pragma unroll
            for (int j = 0; j < 4; j++) { cs[j] += acc[i][j]; cq[j] += acc[i][j] * acc[i][j]; }
        }
    }
    tile_stats(red, ty, c0, cs, cq, &g_stats[384], &g_stats[448]);
}

// ---------------- head ----------------
__global__ void k_out(const float* Wp, const float* bp, float* out) {
    int w = threadIdx.x >> 5, lane = threadIdx.x & 31;
    int n = blockIdx.x * 8 + w;
    if (n >= NN) return;
    float v0 = g_y4[(size_t)n * EMBD + lane];
    float v1 = g_y4[(size_t)n * EMBD + 32 + lane];
    float u0 = fmaxf(fmaf(v0, g_bn[384 + lane], g_bn[448 + lane]), 0.f);
    float u1 = fmaxf(fmaf(v1, g_bn[384 + 32 + lane], g_bn[448 + 32 + lane]), 0.f);
    float t = u0 * Wp[lane] + u1 * Wp[32 + lane];
#pragma unroll
    for (int o = 16; o; o >>= 1) t += __shfl_down_sync(0xffffffff, t, o);
    if (lane == 0) out[n] = t + bp[0];
}

extern "C" void kernel_launch(void* const* d_in, const int* in_sizes, int n_in,
                              void* d_out, int out_size) {
    const float* pos  = (const float*)d_in[0];
    const float* vel  = (const float*)d_in[1];
    const void*  ei   = d_in[2];
    const float* W_in = (const float*)d_in[3];
    const float* b_in = (const float*)d_in[4];
    const float* mW1  = (const float*)d_in[5];
    const float* mb1  = (const float*)d_in[6];
    const float* mg1  = (const float*)d_in[7];
    const float* mB1  = (const float*)d_in[8];
    const float* mW2  = (const float*)d_in[9];
    const float* mb2  = (const float*)d_in[10];
    const float* mg2  = (const float*)d_in[11];
    const float* mB2  = (const float*)d_in[12];
    const float* uW1  = (const float*)d_in[13];
    const float* ub1  = (const float*)d_in[14];
    const float* ug1  = (const float*)d_in[15];
    const float* uB1  = (const float*)d_in[16];
    const float* uW2  = (const float*)d_in[17];
    const float* ub2  = (const float*)d_in[18];
    const float* ug2  = (const float*)d_in[19];
    const float* uB2  = (const float*)d_in[20];
    const float* Wp   = (const float*)d_in[21];
    const float* bp   = (const float*)d_in[22];
    float* out = (float*)d_out;
    (void)in_sizes; (void)n_in; (void)out_size;

    k_init<<<(NN + 255) / 256, 256>>>((const unsigned int*)ei);
    k_conv<<<(NE + 255) / 256, 256>>>(ei);
    k_scanA<<<SCANB, 256>>>();
    k_scanB<<<1, 128>>>();
    k_scanC<<<SCANB, 1024>>>();
    k_scatter<<<(NE + 255) / 256, 256>>>();
    k_pre<<<3, 256>>>(W_in, b_in, mW1, mb1, uW1, ub1);
    k_pq<<<(NN * EMBD + 255) / 256, 256>>>(pos, vel);
    k_momE<<<512, 256>>>();
    k_momN<<<128, 256>>>();
    k_bnmom<<<1, 64>>>(mg1, mB1);
    k_e2<<<444, 256>>>(mW2, mb2);
    k_bn<<<1, 64>>>(1, (float)NE, mg2, mB2);
    k_e3<<<(NN * 8 + 255) / 256, 256>>>();
    k_u1<<<(NN + 63) / 64, 256>>>(pos, vel, uW1);
    k_bn<<<1, 64>>>(2, (float)NN, ug1, uB1);
    k_u2<<<(NN + 63) / 64, 256>>>(uW2, ub2);
    k_bn<<<1, 64>>>(3, (float)NN, ug2, uB2);
    k_out<<<(NN + 7) / 8, 256>>>(Wp, bp, out);
}

// round 16
// speedup vs baseline: 1.0461x; 1.0461x over previous
#include <cuda_runtime.h>
#include <cuda_fp16.h>
#include <math.h>

#define NN 100000
#define NE 1600000
#define EMBD 64
#define EPSBN 1e-5f
#define NTILE (NE / 64)          // 25000
#define SCANB 98                 // ceil(NN/1024)

// ---------------- scratch (static device globals; no allocation) ----------------
__device__ __align__(16) float g_p[(size_t)NN * EMBD];
__device__ __align__(16) float g_q[(size_t)NN * EMBD];
__device__ __align__(16) float g_aggr[(size_t)NN * EMBD];
__device__ __align__(16) __half g_y2h[(size_t)NE * EMBD];   // 204.8 MB (fp16, dst-sorted edge order)
__device__ __align__(16) float g_y3[(size_t)NN * EMBD];
__device__ __align__(16) float g_y4[(size_t)NN * EMBD];
__device__ __align__(16) float4 g_x[NN];   // packed node features (pos.xy, vel.xy), 1.6 MB
__device__ int g_src[NE];
__device__ int g_dst[NE];
__device__ __align__(8) int2 g_se[NE];   // sorted edges: .x = dst, .y = src
__device__ int g_cnt[NN];         // indeg
__device__ int g_outc[NN];        // outdeg
__device__ int g_off[NN + 1];
__device__ int g_cur[NN];
__device__ int g_bsum[SCANB];
__device__ int g_bpre[SCANB];
__device__ float g_Cp[4 * EMBD];
__device__ float g_Cq[4 * EMBD];
__device__ float g_Cu[4 * EMBD];
__device__ float g_cb1[EMBD];
__device__ float g_cbu[EMBD];
__device__ float g_stats[8 * EMBD];
__device__ float g_bn[8 * EMBD];
// moments: [0:16) Mds, [16:32) Mdd, [32:48) Mss, [48:52) vd, [52:56) vs
__device__ float g_mom[56];
__device__ int g_is64;

__device__ __forceinline__ unsigned smem_u32(const void* p) {
    return (unsigned)__cvta_generic_to_shared(p);
}

// ---------------- init: zero cnt/outc/stats/mom; block 0 also detects int64 vs int32 ----------------
__global__ void k_init(const unsigned int* w) {
    int i = blockIdx.x * blockDim.x + threadIdx.x;
    if (i < NN) { g_cnt[i] = 0; g_outc[i] = 0; }
    if (blockIdx.x < 2) g_stats[blockIdx.x * 256 + threadIdx.x] = 0.f;
    if (blockIdx.x == 2 && threadIdx.x < 56) g_mom[threadIdx.x] = 0.f;
    if (blockIdx.x == 0) {
        __shared__ int bad;
        if (threadIdx.x == 0) bad = 0;
        __syncthreads();
        for (int k = 1 + 2 * threadIdx.x; k < 4096; k += 2 * blockDim.x)
            if (w[k] != 0u) bad = 1;
        __syncthreads();
        if (threadIdx.x == 0) g_is64 = bad ? 0 : 1;
    }
}

// ---------------- convert indices + dst/src histograms (fused) ----------------
__global__ void k_conv(const void* ei) {
    int e = blockIdx.x * blockDim.x + threadIdx.x;
    if (e >= NE) return;
    int s, d;
    if (g_is64) {
        const long long* p = (const long long*)ei;
        s = (int)p[e];
        d = (int)p[(size_t)NE + e];
    } else {
        const int* p = (const int*)ei;
        s = p[e];
        d = p[NE + e];
    }
    g_src[e] = s;
    g_dst[e] = d;
    atomicAdd(&g_cnt[d], 1);
    atomicAdd(&g_outc[s], 1);
}

// ---------------- 3-phase parallel exclusive scan ----------------
__global__ void k_scanA() {
    __shared__ int wsum[8];
    int b = blockIdx.x, t = threadIdx.x;
    int base = b * 1024;
    int s = 0;
    for (int i = t; i < 1024; i += 256) {
        int idx = base + i;
        s += (idx < NN) ? g_cnt[idx] : 0;
    }
#pragma unroll
    for (int o = 16; o; o >>= 1) s += __shfl_down_sync(0xffffffffu, s, o);
    if ((t & 31) == 0) wsum[t >> 5] = s;
    __syncthreads();
    if (t == 0) {
        int tot = 0;
#pragma unroll
        for (int i = 0; i < 8; i++) tot += wsum[i];
        g_bsum[b] = tot;
    }
}

__global__ void k_scanB() {
    __shared__ int sh[SCANB];
    int t = threadIdx.x;
    if (t < SCANB) sh[t] = g_bsum[t];
    __syncthreads();
    if (t == 0) {
        int run = 0;
        for (int i = 0; i < SCANB; i++) { int c = sh[i]; sh[i] = run; run += c; }
    }
    __syncthreads();
    if (t < SCANB) g_bpre[t] = sh[t];
}

__global__ void k_scanC() {
    __shared__ int ws[32];
    int b = blockIdx.x, t = threadIdx.x;
    int idx = b * 1024 + t;
    int v = (idx < NN) ? g_cnt[idx] : 0;
    int lane = t & 31, w = t >> 5;
    int incl = v;
#pragma unroll
    for (int o = 1; o < 32; o <<= 1) { int u = __shfl_up_sync(0xffffffffu, incl, o); if (lane >= o) incl += u; }
    if (lane == 31) ws[w] = incl;
    __syncthreads();
    if (w == 0) {
        int x = ws[lane];
#pragma unroll
        for (int o = 1; o < 32; o <<= 1) { int u = __shfl_up_sync(0xffffffffu, x, o); if (lane >= o) x += u; }
        ws[lane] = x;
    }
    __syncthreads();
    int excl = incl - v + (w > 0 ? ws[w - 1] : 0) + g_bpre[b];
    if (idx < NN) { g_off[idx] = excl; g_cur[idx] = excl; }
    if (idx == 0) g_off[NN] = NE;
}

__global__ void k_scatter() {
    int e = blockIdx.x * blockDim.x + threadIdx.x;
    if (e >= NE) return;
    int d = g_dst[e];
    int pos = atomicAdd(&g_cur[d], 1);
    g_se[pos] = make_int2(d, g_src[e]);
}

// ---------------- composite 4x64 matrices (3 concurrent blocks) ----------------
__global__ void k_pre(const float* W_in, const float* b_in,
                      const float* mW1, const float* mb1,
                      const float* uW1, const float* ub1) {
    int tid = threadIdx.x;
    int f = tid >> 6, c = tid & 63;
    int m = blockIdx.x;
    const float* W = (m == 0) ? mW1 : (m == 1) ? (mW1 + 64 * EMBD) : uW1;
    float s = 0.f;
#pragma unroll 8
    for (int k = 0; k < EMBD; k++) s += W_in[f * EMBD + k] * W[k * EMBD + c];
    float* C = (m == 0) ? g_Cp : (m == 1) ? g_Cq : g_Cu;
    C[tid] = s;
    if (f == 0) {
        if (m == 0) {
            float s1 = mb1[c];
#pragma unroll 8
            for (int k = 0; k < EMBD; k++)
                s1 += b_in[k] * (mW1[k * EMBD + c] + mW1[(EMBD + k) * EMBD + c]);
            g_cb1[c] = s1;
        } else if (m == 2) {
            float s2 = ub1[c];
#pragma unroll 8
            for (int k = 0; k < EMBD; k++) s2 += b_in[k] * uW1[k * EMBD + c];
            g_cbu[c] = s2;
        }
    }
}

// ---------------- per-node p,q + packed features ----------------
__global__ void k_pq(const float* pos, const float* vel) {
    int i = blockIdx.x * blockDim.x + threadIdx.x;
    if (i >= NN * EMBD) return;
    int n = i >> 6, c = i & 63;
    float x0 = pos[2 * n], x1 = pos[2 * n + 1];
    float x2 = vel[2 * n], x3 = vel[2 * n + 1];
    g_p[i] = x0 * g_Cp[c] + x1 * g_Cp[64 + c] + x2 * g_Cp[128 + c] + x3 * g_Cp[192 + c];
    g_q[i] = x0 * g_Cq[c] + x1 * g_Cq[64 + c] + x2 * g_Cq[128 + c] + x3 * g_Cq[192 + c];
    if (c == 0) g_x[n] = make_float4(x0, x1, x2, x3);
}

// ---------------- edge moment pass: Mds[i][j] = sum_e x_dst[i]*x_src[j]  (sorted edges: xd L1-hits) ----------------
__global__ void __launch_bounds__(256) k_momE() {
    float m[16];
#pragma unroll
    for (int k = 0; k < 16; k++) m[k] = 0.f;
    int stride = gridDim.x * blockDim.x;
    for (int e = blockIdx.x * blockDim.x + threadIdx.x; e < NE; e += stride) {
        int2 v = g_se[e];
        float4 xd = g_x[v.x];
        float4 xs = g_x[v.y];
        const float* a = &xd.x;
        const float* b = &xs.x;
#pragma unroll
        for (int i = 0; i < 4; i++)
#pragma unroll
            for (int j = 0; j < 4; j++)
                m[i * 4 + j] = fmaf(a[i], b[j], m[i * 4 + j]);
    }
    __shared__ float sh[8][16];
    int lane = threadIdx.x & 31, w = threadIdx.x >> 5;
#pragma unroll
    for (int k = 0; k < 16; k++) {
#pragma unroll
        for (int o = 16; o; o >>= 1) m[k] += __shfl_down_sync(0xffffffffu, m[k], o);
    }
    if (lane == 0) {
#pragma unroll
        for (int k = 0; k < 16; k++) sh[w][k] = m[k];
    }
    __syncthreads();
    if (w == 0 && lane < 16) {
        float t = 0.f;
#pragma unroll
        for (int y = 0; y < 8; y++) t += sh[y][lane];
        atomicAdd(&g_mom[lane], t);
    }
}

// ---------------- node moment pass: Mdd, Mss, vd, vs (degree-weighted) ----------------
__global__ void __launch_bounds__(256) k_momN() {
    float mdd[16], mss[16], vd[4], vs[4];
#pragma unroll
    for (int k = 0; k < 16; k++) { mdd[k] = 0.f; mss[k] = 0.f; }
#pragma unroll
    for (int k = 0; k < 4; k++) { vd[k] = 0.f; vs[k] = 0.f; }
    int stride = gridDim.x * blockDim.x;
    for (int n = blockIdx.x * blockDim.x + threadIdx.x; n < NN; n += stride) {
        float4 x = g_x[n];
        const float* a = &x.x;
        float wi = (float)g_cnt[n], wo = (float)g_outc[n];
#pragma unroll
        for (int i = 0; i < 4; i++) {
            vd[i] = fmaf(wi, a[i], vd[i]);
            vs[i] = fmaf(wo, a[i], vs[i]);
#pragma unroll
            for (int j = 0; j < 4; j++) {
                float pij = a[i] * a[j];
                mdd[i * 4 + j] = fmaf(wi, pij, mdd[i * 4 + j]);
                mss[i * 4 + j] = fmaf(wo, pij, mss[i * 4 + j]);
            }
        }
    }
    __shared__ float sh[8][40];
    int lane = threadIdx.x & 31, w = threadIdx.x >> 5;
#pragma unroll
    for (int k = 0; k < 16; k++) {
#pragma unroll
        for (int o = 16; o; o >>= 1) {
            mdd[k] += __shfl_down_sync(0xffffffffu, mdd[k], o);
            mss[k] += __shfl_down_sync(0xffffffffu, mss[k], o);
        }
    }
#pragma unroll
    for (int k = 0; k < 4; k++) {
#pragma unroll
        for (int o = 16; o; o >>= 1) {
            vd[k] += __shfl_down_sync(0xffffffffu, vd[k], o);
            vs[k] += __shfl_down_sync(0xffffffffu, vs[k], o);
        }
    }
    if (lane == 0) {
#pragma unroll
        for (int k = 0; k < 16; k++) { sh[w][k] = mdd[k]; sh[w][16 + k] = mss[k]; }
#pragma unroll
        for (int k = 0; k < 4; k++) { sh[w][32 + k] = vd[k]; sh[w][36 + k] = vs[k]; }
    }
    __syncthreads();
    if (w == 0) {
        float t = 0.f;
#pragma unroll
        for (int y = 0; y < 8; y++) t += sh[y][lane];
        atomicAdd(&g_mom[16 + lane], t);
    }
    if (w == 1 && lane < 8) {
        float t = 0.f;
#pragma unroll
        for (int y = 0; y < 8; y++) t += sh[y][32 + lane];
        atomicAdd(&g_mom[48 + lane], t);
    }
}

// ---------------- BN1 coefficients from moments ----------------
__global__ void k_bnmom(const float* gamma, const float* beta) {
    __shared__ float mom[56];
    int c = threadIdx.x;
    if (c < 56) mom[c] = g_mom[c];
    __syncthreads();
    float Cp[4], Cq[4];
#pragma unroll
    for (int i = 0; i < 4; i++) { Cp[i] = g_Cp[i * 64 + c]; Cq[i] = g_Cq[i * 64 + c]; }
    float cb = g_cb1[c];
    float sp = 0.f, sq = 0.f;
#pragma unroll
    for (int i = 0; i < 4; i++) { sp += mom[48 + i] * Cp[i]; sq += mom[52 + i] * Cq[i]; }
    float S1 = sp + sq + (float)NE * cb;
    float q2 = 0.f;
#pragma unroll
    for (int i = 0; i < 4; i++)
#pragma unroll
        for (int j = 0; j < 4; j++) {
            q2 += Cp[i] * Cp[j] * mom[16 + i * 4 + j];
            q2 += Cq[i] * Cq[j] * mom[32 + i * 4 + j];
            q2 += 2.f * Cp[i] * Cq[j] * mom[i * 4 + j];
        }
    float S2 = q2 + 2.f * cb * (sp + sq) + (float)NE * cb * cb;
    float mu = S1 / (float)NE;
    float var = S2 / (float)NE - mu * mu;
    float a = gamma[c] * rsqrtf(fmaxf(var, 0.f) + EPSBN);
    g_bn[c] = a;
    g_bn[64 + c] = beta[c] - mu * a;
}

// ---------------- fold BN stats into per-channel (a, s) — layers 1..3 ----------------
__global__ void k_bn(int layer, float cnt, const float* gamma, const float* beta) {
    int c = threadIdx.x;
    float mu = g_stats[layer * 128 + c] / cnt;
    float v  = g_stats[layer * 128 + 64 + c] / cnt - mu * mu;
    float a  = gamma[c] * rsqrtf(fmaxf(v, 0.f) + EPSBN);
    g_bn[layer * 128 + c] = a;
    g_bn[layer * 128 + 64 + c] = beta[c] - mu * a;
}

// ---------------- scalar 64x64 register-blocked GEMM core (node kernels) ----------------
__device__ __forceinline__ void tile_gemm(const float (*zs)[68], const float (*sw)[64],
                                          int r0, int c0, float acc[4][4]) {
#pragma unroll
    for (int k = 0; k < 64; k += 4) {
        float4 A0 = *(const float4*)&zs[r0 + 0][k];
        float4 A1 = *(const float4*)&zs[r0 + 1][k];
        float4 A2 = *(const float4*)&zs[r0 + 2][k];
        float4 A3 = *(const float4*)&zs[r0 + 3][k];
        const float* a0 = (const float*)&A0;
        const float* a1 = (const float*)&A1;
        const float* a2 = (const float*)&A2;
        const float* a3 = (const float*)&A3;
#pragma unroll
        for (int kk = 0; kk < 4; kk++) {
            float4 B = *(const float4*)&sw[k + kk][c0];
            acc[0][0] = fmaf(a0[kk], B.x, acc[0][0]);
            acc[0][1] = fmaf(a0[kk], B.y, acc[0][1]);
            acc[0][2] = fmaf(a0[kk], B.z, acc[0][2]);
            acc[0][3] = fmaf(a0[kk], B.w, acc[0][3]);
            acc[1][0] = fmaf(a1[kk], B.x, acc[1][0]);
            acc[1][1] = fmaf(a1[kk], B.y, acc[1][1]);
            acc[1][2] = fmaf(a1[kk], B.z, acc[1][2]);
            acc[1][3] = fmaf(a1[kk], B.w, acc[1][3]);
            acc[2][0] = fmaf(a2[kk], B.x, acc[2][0]);
            acc[2][1] = fmaf(a2[kk], B.y, acc[2][1]);
            acc[2][2] = fmaf(a2[kk], B.z, acc[2][2]);
            acc[2][3] = fmaf(a2[kk], B.w, acc[2][3]);
            acc[3][0] = fmaf(a3[kk], B.x, acc[3][0]);
            acc[3][1] = fmaf(a3[kk], B.y, acc[3][1]);
            acc[3][2] = fmaf(a3[kk], B.z, acc[3][2]);
            acc[3][3] = fmaf(a3[kk], B.w, acc[3][3]);
        }
    }
}

__device__ __forceinline__ void tile_stats(float red[16][64], int ty, int c0,
                                           const float cs[4], const float cq[4],
                                           float* gsum, float* gsq) {
    int tid = threadIdx.x;
#pragma unroll
    for (int j = 0; j < 4; j++) red[ty][c0 + j] = cs[j];
    __syncthreads();
    if (tid < 64) {
        float t = 0.f;
#pragma unroll
        for (int y = 0; y < 16; y++) t += red[y][tid];
        atomicAdd(&gsum[tid], t);
    }
    __syncthreads();
#pragma unroll
    for (int j = 0; j < 4; j++) red[ty][c0 + j] = cq[j];
    __syncthreads();
    if (tid < 64) {
        float t = 0.f;
#pragma unroll
        for (int y = 0; y < 16; y++) t += red[y][tid];
        atomicAdd(&gsq[tid], t);
    }
}

// ---------------- edge layer 2: PERSISTENT tensor-core GEMM, double-buffered pipeline ----------------
__global__ void __launch_bounds__(256, 3) k_e2(const float* mW2, const float* mb2) {
    __shared__ __align__(16) __half zh[2][64][72];
    __shared__ __align__(16) __half wh[64][72];
    __shared__ float red[32][64];
    int tid = threadIdx.x;
#pragma unroll
    for (int i = 0; i < 16; i++) {
        int idx = i * 256 + tid;
        wh[idx >> 6][idx & 63] = __float2half(mW2[idx]);
    }
    int w = tid >> 5, lane = tid & 31;
    int m0 = (w & 3) * 16, n0b = (w >> 2) * 32;
    int grp = lane >> 3, li = lane & 7;
    int arow = m0 + li + (grp & 1) * 8;
    int akoff = (grp >> 1) * 8;
    unsigned zbase0 = smem_u32(&zh[0][0][0]);
    unsigned wbase = smem_u32(&wh[0][0]);
    const unsigned ZBUF = 64 * 72 * 2;
    int cg4 = (tid & 15) * 4;
    int rl = tid >> 4;
    float4 bn_cb = *(const float4*)&g_cb1[cg4];
    float4 bn_a  = *(const float4*)&g_bn[cg4];
    float4 bn_s  = *(const float4*)&g_bn[64 + cg4];
    float bias0[4][2];
#pragma unroll
    for (int q = 0; q < 4; q++) {
        int c = n0b + q * 8 + (lane & 3) * 2;
        bias0[q][0] = mb2[c]; bias0[q][1] = mb2[c + 1];
    }
    int r0s = m0 + (lane >> 2), r1s = r0s + 8;
    float scs[4][2] = {{0.f,0.f},{0.f,0.f},{0.f,0.f},{0.f,0.f}};
    float scq[4][2] = {{0.f,0.f},{0.f,0.f},{0.f,0.f},{0.f,0.f}};

    {
        int e0 = blockIdx.x * 64;
#pragma unroll
        for (int j = 0; j < 4; j++) {
            int r = rl + 16 * j;
            int2 v = g_se[e0 + r];
            float4 pp = *(const float4*)&g_p[(size_t)v.x * EMBD + cg4];
            float4 qq = *(const float4*)&g_q[(size_t)v.y * EMBD + cg4];
            __half2 h0 = __floats2half2_rn(
                fmaxf(fmaf(pp.x + qq.x + bn_cb.x, bn_a.x, bn_s.x), 0.f),
                fmaxf(fmaf(pp.y + qq.y + bn_cb.y, bn_a.y, bn_s.y), 0.f));
            __half2 h1 = __floats2half2_rn(
                fmaxf(fmaf(pp.z + qq.z + bn_cb.z, bn_a.z, bn_s.z), 0.f),
                fmaxf(fmaf(pp.w + qq.w + bn_cb.w, bn_a.w, bn_s.w), 0.f));
            uint2 u; u.x = *(unsigned*)&h0; u.y = *(unsigned*)&h1;
            *(uint2*)&zh[0][r][cg4] = u;
        }
    }
    __syncthreads();

    int buf = 0;
    for (int tile = blockIdx.x; tile < NTILE; tile += gridDim.x) {
        int e0 = tile * 64;
        int nxt = tile + gridDim.x;
        if (nxt < NTILE) {
            int f0 = nxt * 64;
#pragma unroll
            for (int j = 0; j < 4; j++) {
                int r = rl + 16 * j;
                int2 v = g_se[f0 + r];
                float4 pp = *(const float4*)&g_p[(size_t)v.x * EMBD + cg4];
                float4 qq = *(const float4*)&g_q[(size_t)v.y * EMBD + cg4];
                __half2 h0 = __floats2half2_rn(
                    fmaxf(fmaf(pp.x + qq.x + bn_cb.x, bn_a.x, bn_s.x), 0.f),
                    fmaxf(fmaf(pp.y + qq.y + bn_cb.y, bn_a.y, bn_s.y), 0.f));
                __half2 h1 = __floats2half2_rn(
                    fmaxf(fmaf(pp.z + qq.z + bn_cb.z, bn_a.z, bn_s.z), 0.f),
                    fmaxf(fmaf(pp.w + qq.w + bn_cb.w, bn_a.w, bn_s.w), 0.f));
                uint2 u; u.x = *(unsigned*)&h0; u.y = *(unsigned*)&h1;
                *(uint2*)&zh[buf ^ 1][r][cg4] = u;
            }
        }
        unsigned zb = zbase0 + (unsigned)buf * ZBUF;
        float acc[4][4];
#pragma unroll
        for (int q = 0; q < 4; q++) {
            acc[q][0] = bias0[q][0]; acc[q][1] = bias0[q][1];
            acc[q][2] = bias0[q][0]; acc[q][3] = bias0[q][1];
        }
#pragma unroll
        for (int ks = 0; ks < 4; ks++) {
            int k0 = ks * 16;
            unsigned a0, a1, a2, a3;
            unsigned aaddr = zb + (unsigned)(arow * 144 + (k0 + akoff) * 2);
            asm volatile("ldmatrix.sync.aligned.m8n8.x4.shared.b16 {%0,%1,%2,%3}, [%4];"
                         : "=r"(a0), "=r"(a1), "=r"(a2), "=r"(a3) : "r"(aaddr));
#pragma unroll
            for (int q = 0; q < 4; q++) {
                int n0 = n0b + q * 8;
                unsigned baddr = wbase + (unsigned)((k0 + (lane & 15)) * 144 + n0 * 2);
                unsigned b0, b1;
                asm volatile("ldmatrix.sync.aligned.m8n8.x2.trans.shared.b16 {%0,%1}, [%2];"
                             : "=r"(b0), "=r"(b1) : "r"(baddr));
                asm volatile("mma.sync.aligned.m16n8k16.row.col.f32.f16.f16.f32 "
                             "{%0,%1,%2,%3}, {%4,%5,%6,%7}, {%8,%9}, {%0,%1,%2,%3};"
                             : "+f"(acc[q][0]), "+f"(acc[q][1]), "+f"(acc[q][2]), "+f"(acc[q][3])
                             : "r"(a0), "r"(a1), "r"(a2), "r"(a3), "r"(b0), "r"(b1));
            }
        }
#pragma unroll
        for (int q = 0; q < 4; q++) {
            int c = n0b + q * 8 + (lane & 3) * 2;
            *(__half2*)&g_y2h[(size_t)(e0 + r0s) * EMBD + c] = __floats2half2_rn(acc[q][0], acc[q][1]);
            *(__half2*)&g_y2h[(size_t)(e0 + r1s) * EMBD + c] = __floats2half2_rn(acc[q][2], acc[q][3]);
            scs[q][0] += acc[q][0] + acc[q][2];
            scs[q][1] += acc[q][1] + acc[q][3];
            scq[q][0] += acc[q][0] * acc[q][0] + acc[q][2] * acc[q][2];
            scq[q][1] += acc[q][1] * acc[q][1] + acc[q][3] * acc[q][3];
        }
        __syncthreads();
        buf ^= 1;
    }

    int ridx = (w & 3) * 8 + (lane >> 2);
#pragma unroll
    for (int q = 0; q < 4; q++) {
        int c = n0b + q * 8 + (lane & 3) * 2;
        red[ridx][c] = scs[q][0]; red[ridx][c + 1] = scs[q][1];
    }
    __syncthreads();
    if (tid < 64) {
        float t = 0.f;
#pragma unroll
        for (int y = 0; y < 32; y++) t += red[y][tid];
        atomicAdd(&g_stats[128 + tid], t);
    }
    __syncthreads();
#pragma unroll
    for (int q = 0; q < 4; q++) {
        int c = n0b + q * 8 + (lane & 3) * 2;
        red[ridx][c] = scq[q][0]; red[ridx][c + 1] = scq[q][1];
    }
    __syncthreads();
    if (tid < 64) {
        float t = 0.f;
#pragma unroll
        for (int y = 0; y < 32; y++) t += red[y][tid];
        atomicAdd(&g_stats[192 + tid], t);
    }
}

// ---------------- segment-sum aggregation (NO atomics) ----------------
__global__ void __launch_bounds__(256) k_e3() {
    int gid = blockIdx.x * blockDim.x + threadIdx.x;
    int n = gid >> 3;
    if (n >= NN) return;
    int c = (gid & 7) * 8;
    float4 ba0 = *(const float4*)&g_bn[128 + c];
    float4 ba1 = *(const float4*)&g_bn[128 + c + 4];
    float4 bs0 = *(const float4*)&g_bn[192 + c];
    float4 bs1 = *(const float4*)&g_bn[192 + c + 4];
    int t0 = g_off[n], t1 = g_off[n + 1];
    float a0 = 0.f, a1 = 0.f, a2 = 0.f, a3 = 0.f, a4 = 0.f, a5 = 0.f, a6 = 0.f, a7 = 0.f;
    for (int t = t0; t < t1; t++) {
        uint4 raw = *(const uint4*)&g_y2h[((size_t)t << 6) + c];
        float2 f0 = __half22float2(*(__half2*)&raw.x);
        float2 f1 = __half22float2(*(__half2*)&raw.y);
        float2 f2 = __half22float2(*(__half2*)&raw.z);
        float2 f3 = __half22float2(*(__half2*)&raw.w);
        a0 += fmaxf(fmaf(f0.x, ba0.x, bs0.x), 0.f);
        a1 += fmaxf(fmaf(f0.y, ba0.y, bs0.y), 0.f);
        a2 += fmaxf(fmaf(f1.x, ba0.z, bs0.z), 0.f);
        a3 += fmaxf(fmaf(f1.y, ba0.w, bs0.w), 0.f);
        a4 += fmaxf(fmaf(f2.x, ba1.x, bs1.x), 0.f);
        a5 += fmaxf(fmaf(f2.y, ba1.y, bs1.y), 0.f);
        a6 += fmaxf(fmaf(f3.x, ba1.z, bs1.z), 0.f);
        a7 += fmaxf(fmaf(f3.y, ba1.w, bs1.w), 0.f);
    }
    float* dp = &g_aggr[(size_t)n * EMBD + c];
    *(float4*)dp       = make_float4(a0, a1, a2, a3);
    *(float4*)(dp + 4) = make_float4(a4, a5, a6, a7);
}

// ---------------- node layer 1 ----------------
__global__ void __launch_bounds__(256) k_u1(const float* pos, const float* vel, const float* uW1) {
    __shared__ __align__(16) float as_[64][68];
    __shared__ __align__(16) float sw[64][64];
    __shared__ float red[16][64];
    __shared__ float sx[64][4];
    int tid = threadIdx.x;
    int n0 = blockIdx.x * 64;
#pragma unroll
    for (int i = 0; i < 16; i++) { int idx = i * 256 + tid; sw[idx >> 6][idx & 63] = uW1[4096 + idx]; }
    if (tid < 64) {
        int n = n0 + tid;
        if (n < NN) {
            sx[tid][0] = pos[2 * n]; sx[tid][1] = pos[2 * n + 1];
            sx[tid][2] = vel[2 * n]; sx[tid][3] = vel[2 * n + 1];
        } else {
            sx[tid][0] = sx[tid][1] = sx[tid][2] = sx[tid][3] = 0.f;
        }
    }
    {
        int c = tid & 63, l = tid >> 6;
#pragma unroll
        for (int j = 0; j < 16; j++) {
            int r = l + 4 * j; int n = n0 + r;
            as_[r][c] = (n < NN) ? g_aggr[(size_t)n * EMBD + c] : 0.f;
        }
    }
    __syncthreads();
    int tx = tid & 15, ty = tid >> 4;
    int c0 = tx * 4, r0 = ty * 4;
    float acc[4][4];
#pragma unroll
    for (int i = 0; i < 4; i++) {
        int r = r0 + i;
#pragma unroll
        for (int j = 0; j < 4; j++) {
            int c = c0 + j;
            acc[i][j] = g_cbu[c] + sx[r][0] * g_Cu[c] + sx[r][1] * g_Cu[64 + c]
                      + sx[r][2] * g_Cu[128 + c] + sx[r][3] * g_Cu[192 + c];
        }
    }
    tile_gemm(as_, sw, r0, c0, acc);
    float cs[4] = {0, 0, 0, 0}, cq[4] = {0, 0, 0, 0};
#pragma unroll
    for (int i = 0; i < 4; i++) {
        int n = n0 + r0 + i;
        if (n < NN) {
            float4 o; o.x = acc[i][0]; o.y = acc[i][1]; o.z = acc[i][2]; o.w = acc[i][3];
            *(float4*)&g_y3[(size_t)n * EMBD + c0] = o;
#pragma unroll
            for (int j = 0; j < 4; j++) { cs[j] += acc[i][j]; cq[j] += acc[i][j] * acc[i][j]; }
        }
    }
    tile_stats(red, ty, c0, cs, cq, &g_stats[256], &g_stats[320]);
}

// ---------------- node layer 2 ----------------
__global__ void __launch_bounds__(256) k_u2(const float* uW2, const float* ub2) {
    __shared__ __align__(16) float as_[64][68];
    __shared__ __align__(16) float sw[64][64];
    __shared__ float red[16][64];
    int tid = threadIdx.x;
    int n0 = blockIdx.x * 64;
#pragma unroll
    for (int i = 0; i < 16; i++) { int idx = i * 256 + tid; sw[idx >> 6][idx & 63] = uW2[idx]; }
    {
        int c = tid & 63, l = tid >> 6;
        float a3 = g_bn[256 + c], s3 = g_bn[320 + c];
#pragma unroll
        for (int j = 0; j < 16; j++) {
            int r = l + 4 * j; int n = n0 + r;
            as_[r][c] = (n < NN) ? fmaxf(fmaf(g_y3[(size_t)n * EMBD + c], a3, s3), 0.f) : 0.f;
        }
    }
    __syncthreads();
    int tx = tid & 15, ty = tid >> 4;
    int c0 = tx * 4, r0 = ty * 4;
    float acc[4][4];
#pragma unroll
    for (int j = 0; j < 4; j++) {
        float b = ub2[c0 + j];
        acc[0][j] = b; acc[1][j] = b; acc[2][j] = b; acc[3][j] = b;
    }
    tile_gemm(as_, sw, r0, c0, acc);
    float cs[4] = {0, 0, 0, 0}, cq[4] = {0, 0, 0, 0};
#pragma unroll
    for (int i = 0; i < 4; i++) {
        int n = n0 + r0 + i;
        if (n < NN) {
            float4 o; o.x = acc[i][0]; o.y = acc[i][1]; o.z = acc[i][2]; o.w = acc[i][3];
            *(float4*)&g_y4[(size_t)n * EMBD + c0] = o;
#pragma unroll
            for (int j = 0; j < 4; j++) { cs[j] += acc[i][j]; cq[j] += acc[i][j] * acc[i][j]; }
        }
    }
    tile_stats(red, ty, c0, cs, cq, &g_stats[384], &g_stats[448]);
}

// ---------------- head ----------------
__global__ void k_out(const float* Wp, const float* bp, float* out) {
    int w = threadIdx.x >> 5, lane = threadIdx.x & 31;
    int n = blockIdx.x * 8 + w;
    if (n >= NN) return;
    float v0 = g_y4[(size_t)n * EMBD + lane];
    float v1 = g_y4[(size_t)n * EMBD + 32 + lane];
    float u0 = fmaxf(fmaf(v0, g_bn[384 + lane], g_bn[448 + lane]), 0.f);
    float u1 = fmaxf(fmaf(v1, g_bn[384 + 32 + lane], g_bn[448 + 32 + lane]), 0.f);
    float t = u0 * Wp[lane] + u1 * Wp[32 + lane];
#pragma unroll
    for (int o = 16; o; o >>= 1) t += __shfl_down_sync(0xffffffff, t, o);
    if (lane == 0) out[n] = t + bp[0];
}

extern "C" void kernel_launch(void* const* d_in, const int* in_sizes, int n_in,
                              void* d_out, int out_size) {
    const float* pos  = (const float*)d_in[0];
    const float* vel  = (const float*)d_in[1];
    const void*  ei   = d_in[2];
    const float* W_in = (const float*)d_in[3];
    const float* b_in = (const float*)d_in[4];
    const float* mW1  = (const float*)d_in[5];
    const float* mb1  = (const float*)d_in[6];
    const float* mg1  = (const float*)d_in[7];
    const float* mB1  = (const float*)d_in[8];
    const float* mW2  = (const float*)d_in[9];
    const float* mb2  = (const float*)d_in[10];
    const float* mg2  = (const float*)d_in[11];
    const float* mB2  = (const float*)d_in[12];
    const float* uW1  = (const float*)d_in[13];
    const float* ub1  = (const float*)d_in[14];
    const float* ug1  = (const float*)d_in[15];
    const float* uB1  = (const float*)d_in[16];
    const float* uW2  = (const float*)d_in[17];
    const float* ub2  = (const float*)d_in[18];
    const float* ug2  = (const float*)d_in[19];
    const float* uB2  = (const float*)d_in[20];
    const float* Wp   = (const float*)d_in[21];
    const float* bp   = (const float*)d_in[22];
    float* out = (float*)d_out;
    (void)in_sizes; (void)n_in; (void)out_size;

    k_init<<<(NN + 255) / 256, 256>>>((const unsigned int*)ei);
    k_conv<<<(NE + 255) / 256, 256>>>(ei);
    k_scanA<<<SCANB, 256>>>();
    k_scanB<<<1, 128>>>();
    k_scanC<<<SCANB, 1024>>>();
    k_scatter<<<(NE + 255) / 256, 256>>>();
    k_pre<<<3, 256>>>(W_in, b_in, mW1, mb1, uW1, ub1);
    k_pq<<<(NN * EMBD + 255) / 256, 256>>>(pos, vel);
    k_momE<<<512, 256>>>();
    k_momN<<<128, 256>>>();
    k_bnmom<<<1, 64>>>(mg1, mB1);
    k_e2<<<444, 256>>>(mW2, mb2);
    k_bn<<<1, 64>>>(1, (float)NE, mg2, mB2);
    k_e3<<<(NN * 8 + 255) / 256, 256>>>();
    k_u1<<<(NN + 63) / 64, 256>>>(pos, vel, uW1);
    k_bn<<<1, 64>>>(2, (float)NN, ug1, uB1);
    k_u2<<<(NN + 63) / 64, 256>>>(uW2, ub2);
    k_bn<<<1, 64>>>(3, (float)NN, ug2, uB2);
    k_out<<<(NN + 7) / 8, 256>>>(Wp, bp, out);
}

// round 17
// speedup vs baseline: 1.2819x; 1.2254x over previous
#include <cuda_runtime.h>
#include <cuda_fp16.h>
#include <math.h>

#define NN 100000
#define NE 1600000
#define EMBD 64
#define EPSBN 1e-5f
#define NTILE (NE / 64)          // 25000
#define SCANB 98                 // ceil(NN/1024)

// ---------------- scratch (static device globals; no allocation) ----------------
__device__ __align__(16) float g_p[(size_t)NN * EMBD];
__device__ __align__(16) float g_q[(size_t)NN * EMBD];
__device__ __align__(16) float g_aggr[(size_t)NN * EMBD];
__device__ __align__(16) __half g_y2h[(size_t)NE * EMBD];   // 204.8 MB (fp16, dst-sorted edge order)
__device__ __align__(16) float g_y3[(size_t)NN * EMBD];
__device__ __align__(16) float g_y4[(size_t)NN * EMBD];
__device__ int g_src[NE];
__device__ int g_dst[NE];
__device__ __align__(8) int2 g_se[NE];   // sorted edges: .x = dst, .y = src
__device__ int g_cnt[NN];
__device__ int g_off[NN + 1];
__device__ int g_cur[NN];
__device__ int g_bsum[SCANB];
__device__ int g_bpre[SCANB];
__device__ float g_Cp[4 * EMBD];
__device__ float g_Cq[4 * EMBD];
__device__ float g_Cu[4 * EMBD];
__device__ float g_cb1[EMBD];
__device__ float g_cbu[EMBD];
__device__ float g_stats[8 * EMBD];
__device__ float g_bn[8 * EMBD];
__device__ int g_is64;

__device__ __forceinline__ unsigned smem_u32(const void* p) {
    return (unsigned)__cvta_generic_to_shared(p);
}

// ---------------- init: zero cnt/stats; block 0 also detects int64 vs int32 ----------------
__global__ void k_init(const unsigned int* w) {
    int i = blockIdx.x * blockDim.x + threadIdx.x;
    if (i < NN) g_cnt[i] = 0;
    if (blockIdx.x < 2) g_stats[blockIdx.x * 256 + threadIdx.x] = 0.f;
    if (blockIdx.x == 0) {
        __shared__ int bad;
        if (threadIdx.x == 0) bad = 0;
        __syncthreads();
        for (int k = 1 + 2 * threadIdx.x; k < 4096; k += 2 * blockDim.x)
            if (w[k] != 0u) bad = 1;
        __syncthreads();
        if (threadIdx.x == 0) g_is64 = bad ? 0 : 1;
    }
}

// ---------------- convert indices + dst histogram (fused) ----------------
__global__ void k_conv(const void* ei) {
    int e = blockIdx.x * blockDim.x + threadIdx.x;
    if (e >= NE) return;
    int s, d;
    if (g_is64) {
        const long long* p = (const long long*)ei;
        s = (int)p[e];
        d = (int)p[(size_t)NE + e];
    } else {
        const int* p = (const int*)ei;
        s = p[e];
        d = p[NE + e];
    }
    g_src[e] = s;
    g_dst[e] = d;
    atomicAdd(&g_cnt[d], 1);
}

// ---------------- 3-phase parallel exclusive scan ----------------
__global__ void k_scanA() {
    __shared__ int wsum[8];
    int b = blockIdx.x, t = threadIdx.x;
    int base = b * 1024;
    int s = 0;
    for (int i = t; i < 1024; i += 256) {
        int idx = base + i;
        s += (idx < NN) ? g_cnt[idx] : 0;
    }
#pragma unroll
    for (int o = 16; o; o >>= 1) s += __shfl_down_sync(0xffffffffu, s, o);
    if ((t & 31) == 0) wsum[t >> 5] = s;
    __syncthreads();
    if (t == 0) {
        int tot = 0;
#pragma unroll
        for (int i = 0; i < 8; i++) tot += wsum[i];
        g_bsum[b] = tot;
    }
}

__global__ void k_scanB() {
    __shared__ int sh[SCANB];
    int t = threadIdx.x;
    if (t < SCANB) sh[t] = g_bsum[t];
    __syncthreads();
    if (t == 0) {
        int run = 0;
        for (int i = 0; i < SCANB; i++) { int c = sh[i]; sh[i] = run; run += c; }
    }
    __syncthreads();
    if (t < SCANB) g_bpre[t] = sh[t];
}

__global__ void k_scanC() {
    __shared__ int ws[32];
    int b = blockIdx.x, t = threadIdx.x;
    int idx = b * 1024 + t;
    int v = (idx < NN) ? g_cnt[idx] : 0;
    int lane = t & 31, w = t >> 5;
    int incl = v;
#pragma unroll
    for (int o = 1; o < 32; o <<= 1) { int u = __shfl_up_sync(0xffffffffu, incl, o); if (lane >= o) incl += u; }
    if (lane == 31) ws[w] = incl;
    __syncthreads();
    if (w == 0) {
        int x = ws[lane];
#pragma unroll
        for (int o = 1; o < 32; o <<= 1) { int u = __shfl_up_sync(0xffffffffu, x, o); if (lane >= o) x += u; }
        ws[lane] = x;
    }
    __syncthreads();
    int excl = incl - v + (w > 0 ? ws[w - 1] : 0) + g_bpre[b];
    if (idx < NN) { g_off[idx] = excl; g_cur[idx] = excl; }
    if (idx == 0) g_off[NN] = NE;
}

__global__ void k_scatter() {
    int e = blockIdx.x * blockDim.x + threadIdx.x;
    if (e >= NE) return;
    int d = g_dst[e];
    int pos = atomicAdd(&g_cur[d], 1);
    g_se[pos] = make_int2(d, g_src[e]);
}

// ---------------- composite 4x64 matrices (3 concurrent blocks) ----------------
__global__ void k_pre(const float* W_in, const float* b_in,
                      const float* mW1, const float* mb1,
                      const float* uW1, const float* ub1) {
    int tid = threadIdx.x;
    int f = tid >> 6, c = tid & 63;
    int m = blockIdx.x;
    const float* W = (m == 0) ? mW1 : (m == 1) ? (mW1 + 64 * EMBD) : uW1;
    float s = 0.f;
#pragma unroll 8
    for (int k = 0; k < EMBD; k++) s += W_in[f * EMBD + k] * W[k * EMBD + c];
    float* C = (m == 0) ? g_Cp : (m == 1) ? g_Cq : g_Cu;
    C[tid] = s;
    if (f == 0) {
        if (m == 0) {
            float s1 = mb1[c];
#pragma unroll 8
            for (int k = 0; k < EMBD; k++)
                s1 += b_in[k] * (mW1[k * EMBD + c] + mW1[(EMBD + k) * EMBD + c]);
            g_cb1[c] = s1;
        } else if (m == 2) {
            float s2 = ub1[c];
#pragma unroll 8
            for (int k = 0; k < EMBD; k++) s2 += b_in[k] * uW1[k * EMBD + c];
            g_cbu[c] = s2;
        }
    }
}

// ---------------- per-node p,q ----------------
__global__ void k_pq(const float* pos, const float* vel) {
    int i = blockIdx.x * blockDim.x + threadIdx.x;
    if (i >= NN * EMBD) return;
    int n = i >> 6, c = i & 63;
    float x0 = pos[2 * n], x1 = pos[2 * n + 1];
    float x2 = vel[2 * n], x3 = vel[2 * n + 1];
    g_p[i] = x0 * g_Cp[c] + x1 * g_Cp[64 + c] + x2 * g_Cp[128 + c] + x3 * g_Cp[192 + c];
    g_q[i] = x0 * g_Cq[c] + x1 * g_Cq[64 + c] + x2 * g_Cq[128 + c] + x3 * g_Cq[192 + c];
}

// ---------------- BN1 stats: CONTIGUOUS per-lane chunks (p-row L1 reuse) + 2-deep unroll ----------------
// NOTE: also acts as the L2 warm-up pass for k_e2's p/q/se gathers (R15/R16 lesson). Do not remove.
__global__ void __launch_bounds__(256) k_e1() {
    int tid = threadIdx.x;
    int l = tid >> 4;              // 0..15 lane group
    int c = (tid & 15) * 4;        // channel group (half-warp covers one 256B row)
    const int CH = NE / 512;       // 3125 edges per block
    const int LCH = (CH + 15) / 16;   // 196 contiguous edges per lane
    int bstart = blockIdx.x * CH;
    int start = bstart + l * LCH;
    int end = bstart + CH; if (start + LCH < end) end = start + LCH;
    float4 cb = *(const float4*)&g_cb1[c];
    float4 s = make_float4(0.f, 0.f, 0.f, 0.f);
    float4 ss = make_float4(0.f, 0.f, 0.f, 0.f);
    for (int e = start; e < end; e += 2) {
        bool h2 = (e + 1) < end;
        int2 v0 = g_se[e];
        int2 v1 = h2 ? g_se[e + 1] : v0;
        float4 pp0 = *(const float4*)&g_p[(size_t)v0.x * EMBD + c];
        float4 qq0 = *(const float4*)&g_q[(size_t)v0.y * EMBD + c];
        float4 pp1 = *(const float4*)&g_p[(size_t)v1.x * EMBD + c];
        float4 qq1 = *(const float4*)&g_q[(size_t)v1.y * EMBD + c];
        float y0 = pp0.x + qq0.x + cb.x, y1 = pp0.y + qq0.y + cb.y;
        float y2 = pp0.z + qq0.z + cb.z, y3 = pp0.w + qq0.w + cb.w;
        s.x += y0; s.y += y1; s.z += y2; s.w += y3;
        ss.x += y0 * y0; ss.y += y1 * y1; ss.z += y2 * y2; ss.w += y3 * y3;
        if (h2) {
            float z0 = pp1.x + qq1.x + cb.x, z1 = pp1.y + qq1.y + cb.y;
            float z2 = pp1.z + qq1.z + cb.z, z3 = pp1.w + qq1.w + cb.w;
            s.x += z0; s.y += z1; s.z += z2; s.w += z3;
            ss.x += z0 * z0; ss.y += z1 * z1; ss.z += z2 * z2; ss.w += z3 * z3;
        }
    }
    __shared__ __align__(16) float sh[16][64];
    *(float4*)&sh[l][c] = s;
    __syncthreads();
    if (tid < 64) {
        float t = 0.f;
#pragma unroll
        for (int y = 0; y < 16; y++) t += sh[y][tid];
        atomicAdd(&g_stats[tid], t);
    }
    __syncthreads();
    *(float4*)&sh[l][c] = ss;
    __syncthreads();
    if (tid < 64) {
        float t = 0.f;
#pragma unroll
        for (int y = 0; y < 16; y++) t += sh[y][tid];
        atomicAdd(&g_stats[64 + tid], t);
    }
}

// ---------------- fold BN stats into per-channel (a, s) ----------------
__global__ void k_bn(int layer, float cnt, const float* gamma, const float* beta) {
    int c = threadIdx.x;
    float mu = g_stats[layer * 128 + c] / cnt;
    float v  = g_stats[layer * 128 + 64 + c] / cnt - mu * mu;
    float a  = gamma[c] * rsqrtf(fmaxf(v, 0.f) + EPSBN);
    g_bn[layer * 128 + c] = a;
    g_bn[layer * 128 + 64 + c] = beta[c] - mu * a;
}

// ---------------- scalar 64x64 register-blocked GEMM core (node kernels) ----------------
__device__ __forceinline__ void tile_gemm(const float (*zs)[68], const float (*sw)[64],
                                          int r0, int c0, float acc[4][4]) {
#pragma unroll
    for (int k = 0; k < 64; k += 4) {
        float4 A0 = *(const float4*)&zs[r0 + 0][k];
        float4 A1 = *(const float4*)&zs[r0 + 1][k];
        float4 A2 = *(const float4*)&zs[r0 + 2][k];
        float4 A3 = *(const float4*)&zs[r0 + 3][k];
        const float* a0 = (const float*)&A0;
        const float* a1 = (const float*)&A1;
        const float* a2 = (const float*)&A2;
        const float* a3 = (const float*)&A3;
#pragma unroll
        for (int kk = 0; kk < 4; kk++) {
            float4 B = *(const float4*)&sw[k + kk][c0];
            acc[0][0] = fmaf(a0[kk], B.x, acc[0][0]);
            acc[0][1] = fmaf(a0[kk], B.y, acc[0][1]);
            acc[0][2] = fmaf(a0[kk], B.z, acc[0][2]);
            acc[0][3] = fmaf(a0[kk], B.w, acc[0][3]);
            acc[1][0] = fmaf(a1[kk], B.x, acc[1][0]);
            acc[1][1] = fmaf(a1[kk], B.y, acc[1][1]);
            acc[1][2] = fmaf(a1[kk], B.z, acc[1][2]);
            acc[1][3] = fmaf(a1[kk], B.w, acc[1][3]);
            acc[2][0] = fmaf(a2[kk], B.x, acc[2][0]);
            acc[2][1] = fmaf(a2[kk], B.y, acc[2][1]);
            acc[2][2] = fmaf(a2[kk], B.z, acc[2][2]);
            acc[2][3] = fmaf(a2[kk], B.w, acc[2][3]);
            acc[3][0] = fmaf(a3[kk], B.x, acc[3][0]);
            acc[3][1] = fmaf(a3[kk], B.y, acc[3][1]);
            acc[3][2] = fmaf(a3[kk], B.z, acc[3][2]);
            acc[3][3] = fmaf(a3[kk], B.w, acc[3][3]);
        }
    }
}

__device__ __forceinline__ void tile_stats(float red[16][64], int ty, int c0,
                                           const float cs[4], const float cq[4],
                                           float* gsum, float* gsq) {
    int tid = threadIdx.x;
#pragma unroll
    for (int j = 0; j < 4; j++) red[ty][c0 + j] = cs[j];
    __syncthreads();
    if (tid < 64) {
        float t = 0.f;
#pragma unroll
        for (int y = 0; y < 16; y++) t += red[y][tid];
        atomicAdd(&gsum[tid], t);
    }
    __syncthreads();
#pragma unroll
    for (int j = 0; j < 4; j++) red[ty][c0 + j] = cq[j];
    __syncthreads();
    if (tid < 64) {
        float t = 0.f;
#pragma unroll
        for (int y = 0; y < 16; y++) t += red[y][tid];
        atomicAdd(&gsq[tid], t);
    }
}

// ---------------- edge layer 2: PERSISTENT tensor-core GEMM, double-buffered pipeline ----------------
__global__ void __launch_bounds__(256, 3) k_e2(const float* mW2, const float* mb2) {
    __shared__ __align__(16) __half zh[2][64][72];
    __shared__ __align__(16) __half wh[64][72];
    __shared__ float red[32][64];
    int tid = threadIdx.x;
#pragma unroll
    for (int i = 0; i < 16; i++) {
        int idx = i * 256 + tid;
        wh[idx >> 6][idx & 63] = __float2half(mW2[idx]);
    }
    int w = tid >> 5, lane = tid & 31;
    int m0 = (w & 3) * 16, n0b = (w >> 2) * 32;
    int grp = lane >> 3, li = lane & 7;
    int arow = m0 + li + (grp & 1) * 8;
    int akoff = (grp >> 1) * 8;
    unsigned zbase0 = smem_u32(&zh[0][0][0]);
    unsigned wbase = smem_u32(&wh[0][0]);
    const unsigned ZBUF = 64 * 72 * 2;
    int cg4 = (tid & 15) * 4;
    int rl = tid >> 4;
    float4 bn_cb = *(const float4*)&g_cb1[cg4];
    float4 bn_a  = *(const float4*)&g_bn[cg4];
    float4 bn_s  = *(const float4*)&g_bn[64 + cg4];
    float bias0[4][2];
#pragma unroll
    for (int q = 0; q < 4; q++) {
        int c = n0b + q * 8 + (lane & 3) * 2;
        bias0[q][0] = mb2[c]; bias0[q][1] = mb2[c + 1];
    }
    int r0s = m0 + (lane >> 2), r1s = r0s + 8;
    float scs[4][2] = {{0.f,0.f},{0.f,0.f},{0.f,0.f},{0.f,0.f}};
    float scq[4][2] = {{0.f,0.f},{0.f,0.f},{0.f,0.f},{0.f,0.f}};

    {
        int e0 = blockIdx.x * 64;
#pragma unroll
        for (int j = 0; j < 4; j++) {
            int r = rl + 16 * j;
            int2 v = g_se[e0 + r];
            float4 pp = *(const float4*)&g_p[(size_t)v.x * EMBD + cg4];
            float4 qq = *(const float4*)&g_q[(size_t)v.y * EMBD + cg4];
            __half2 h0 = __floats2half2_rn(
                fmaxf(fmaf(pp.x + qq.x + bn_cb.x, bn_a.x, bn_s.x), 0.f),
                fmaxf(fmaf(pp.y + qq.y + bn_cb.y, bn_a.y, bn_s.y), 0.f));
            __half2 h1 = __floats2half2_rn(
                fmaxf(fmaf(pp.z + qq.z + bn_cb.z, bn_a.z, bn_s.z), 0.f),
                fmaxf(fmaf(pp.w + qq.w + bn_cb.w, bn_a.w, bn_s.w), 0.f));
            uint2 u; u.x = *(unsigned*)&h0; u.y = *(unsigned*)&h1;
            *(uint2*)&zh[0][r][cg4] = u;
        }
    }
    __syncthreads();

    int buf = 0;
    for (int tile = blockIdx.x; tile < NTILE; tile += gridDim.x) {
        int e0 = tile * 64;
        int nxt = tile + gridDim.x;
        if (nxt < NTILE) {
            int f0 = nxt * 64;
#pragma unroll
            for (int j = 0; j < 4; j++) {
                int r = rl + 16 * j;
                int2 v = g_se[f0 + r];
                float4 pp = *(const float4*)&g_p[(size_t)v.x * EMBD + cg4];
                float4 qq = *(const float4*)&g_q[(size_t)v.y * EMBD + cg4];
                __half2 h0 = __floats2half2_rn(
                    fmaxf(fmaf(pp.x + qq.x + bn_cb.x, bn_a.x, bn_s.x), 0.f),
                    fmaxf(fmaf(pp.y + qq.y + bn_cb.y, bn_a.y, bn_s.y), 0.f));
                __half2 h1 = __floats2half2_rn(
                    fmaxf(fmaf(pp.z + qq.z + bn_cb.z, bn_a.z, bn_s.z), 0.f),
                    fmaxf(fmaf(pp.w + qq.w + bn_cb.w, bn_a.w, bn_s.w), 0.f));
                uint2 u; u.x = *(unsigned*)&h0; u.y = *(unsigned*)&h1;
                *(uint2*)&zh[buf ^ 1][r][cg4] = u;
            }
        }
        unsigned zb = zbase0 + (unsigned)buf * ZBUF;
        float acc[4][4];
#pragma unroll
        for (int q = 0; q < 4; q++) {
            acc[q][0] = bias0[q][0]; acc[q][1] = bias0[q][1];
            acc[q][2] = bias0[q][0]; acc[q][3] = bias0[q][1];
        }
#pragma unroll
        for (int ks = 0; ks < 4; ks++) {
            int k0 = ks * 16;
            unsigned a0, a1, a2, a3;
            unsigned aaddr = zb + (unsigned)(arow * 144 + (k0 + akoff) * 2);
            asm volatile("ldmatrix.sync.aligned.m8n8.x4.shared.b16 {%0,%1,%2,%3}, [%4];"
                         : "=r"(a0), "=r"(a1), "=r"(a2), "=r"(a3) : "r"(aaddr));
#pragma unroll
            for (int q = 0; q < 4; q++) {
                int n0 = n0b + q * 8;
                unsigned baddr = wbase + (unsigned)((k0 + (lane & 15)) * 144 + n0 * 2);
                unsigned b0, b1;
                asm volatile("ldmatrix.sync.aligned.m8n8.x2.trans.shared.b16 {%0,%1}, [%2];"
                             : "=r"(b0), "=r"(b1) : "r"(baddr));
                asm volatile("mma.sync.aligned.m16n8k16.row.col.f32.f16.f16.f32 "
                             "{%0,%1,%2,%3}, {%4,%5,%6,%7}, {%8,%9}, {%0,%1,%2,%3};"
                             : "+f"(acc[q][0]), "+f"(acc[q][1]), "+f"(acc[q][2]), "+f"(acc[q][3])
                             : "r"(a0), "r"(a1), "r"(a2), "r"(a3), "r"(b0), "r"(b1));
            }
        }
#pragma unroll
        for (int q = 0; q < 4; q++) {
            int c = n0b + q * 8 + (lane & 3) * 2;
            *(__half2*)&g_y2h[(size_t)(e0 + r0s) * EMBD + c] = __floats2half2_rn(acc[q][0], acc[q][1]);
            *(__half2*)&g_y2h[(size_t)(e0 + r1s) * EMBD + c] = __floats2half2_rn(acc[q][2], acc[q][3]);
            scs[q][0] += acc[q][0] + acc[q][2];
            scs[q][1] += acc[q][1] + acc[q][3];
            scq[q][0] += acc[q][0] * acc[q][0] + acc[q][2] * acc[q][2];
            scq[q][1] += acc[q][1] * acc[q][1] + acc[q][3] * acc[q][3];
        }
        __syncthreads();
        buf ^= 1;
    }

    int ridx = (w & 3) * 8 + (lane >> 2);
#pragma unroll
    for (int q = 0; q < 4; q++) {
        int c = n0b + q * 8 + (lane & 3) * 2;
        red[ridx][c] = scs[q][0]; red[ridx][c + 1] = scs[q][1];
    }
    __syncthreads();
    if (tid < 64) {
        float t = 0.f;
#pragma unroll
        for (int y = 0; y < 32; y++) t += red[y][tid];
        atomicAdd(&g_stats[128 + tid], t);
    }
    __syncthreads();
#pragma unroll
    for (int q = 0; q < 4; q++) {
        int c = n0b + q * 8 + (lane & 3) * 2;
        red[ridx][c] = scq[q][0]; red[ridx][c + 1] = scq[q][1];
    }
    __syncthreads();
    if (tid < 64) {
        float t = 0.f;
#pragma unroll
        for (int y = 0; y < 32; y++) t += red[y][tid];
        atomicAdd(&g_stats[192 + tid], t);
    }
}

// ---------------- segment-sum aggregation (NO atomics, 2-deep load unroll) ----------------
__global__ void __launch_bounds__(256) k_e3() {
    int gid = blockIdx.x * blockDim.x + threadIdx.x;
    int n = gid >> 3;
    if (n >= NN) return;
    int c = (gid & 7) * 8;
    float4 ba0 = *(const float4*)&g_bn[128 + c];
    float4 ba1 = *(const float4*)&g_bn[128 + c + 4];
    float4 bs0 = *(const float4*)&g_bn[192 + c];
    float4 bs1 = *(const float4*)&g_bn[192 + c + 4];
    int t0 = g_off[n], t1 = g_off[n + 1];
    float a0 = 0.f, a1 = 0.f, a2 = 0.f, a3 = 0.f, a4 = 0.f, a5 = 0.f, a6 = 0.f, a7 = 0.f;
    int t = t0;
    for (; t + 2 <= t1; t += 2) {
        // two independent 16B loads issued back-to-back (MLP 2)
        uint4 r0 = *(const uint4*)&g_y2h[((size_t)t << 6) + c];
        uint4 r1 = *(const uint4*)&g_y2h[((size_t)(t + 1) << 6) + c];
        {
            float2 f0 = __half22float2(*(__half2*)&r0.x);
            float2 f1 = __half22float2(*(__half2*)&r0.y);
            float2 f2 = __half22float2(*(__half2*)&r0.z);
            float2 f3 = __half22float2(*(__half2*)&r0.w);
            a0 += fmaxf(fmaf(f0.x, ba0.x, bs0.x), 0.f);
            a1 += fmaxf(fmaf(f0.y, ba0.y, bs0.y), 0.f);
            a2 += fmaxf(fmaf(f1.x, ba0.z, bs0.z), 0.f);
            a3 += fmaxf(fmaf(f1.y, ba0.w, bs0.w), 0.f);
            a4 += fmaxf(fmaf(f2.x, ba1.x, bs1.x), 0.f);
            a5 += fmaxf(fmaf(f2.y, ba1.y, bs1.y), 0.f);
            a6 += fmaxf(fmaf(f3.x, ba1.z, bs1.z), 0.f);
            a7 += fmaxf(fmaf(f3.y, ba1.w, bs1.w), 0.f);
        }
        {
            float2 f0 = __half22float2(*(__half2*)&r1.x);
            float2 f1 = __half22float2(*(__half2*)&r1.y);
            float2 f2 = __half22float2(*(__half2*)&r1.z);
            float2 f3 = __half22float2(*(__half2*)&r1.w);
            a0 += fmaxf(fmaf(f0.x, ba0.x, bs0.x), 0.f);
            a1 += fmaxf(fmaf(f0.y, ba0.y, bs0.y), 0.f);
            a2 += fmaxf(fmaf(f1.x, ba0.z, bs0.z), 0.f);
            a3 += fmaxf(fmaf(f1.y, ba0.w, bs0.w), 0.f);
            a4 += fmaxf(fmaf(f2.x, ba1.x, bs1.x), 0.f);
            a5 += fmaxf(fmaf(f2.y, ba1.y, bs1.y), 0.f);
            a6 += fmaxf(fmaf(f3.x, ba1.z, bs1.z), 0.f);
            a7 += fmaxf(fmaf(f3.y, ba1.w, bs1.w), 0.f);
        }
    }
    for (; t < t1; t++) {
        uint4 raw = *(const uint4*)&g_y2h[((size_t)t << 6) + c];
        float2 f0 = __half22float2(*(__half2*)&raw.x);
        float2 f1 = __half22float2(*(__half2*)&raw.y);
        float2 f2 = __half22float2(*(__half2*)&raw.z);
        float2 f3 = __half22float2(*(__half2*)&raw.w);
        a0 += fmaxf(fmaf(f0.x, ba0.x, bs0.x), 0.f);
        a1 += fmaxf(fmaf(f0.y, ba0.y, bs0.y), 0.f);
        a2 += fmaxf(fmaf(f1.x, ba0.z, bs0.z), 0.f);
        a3 += fmaxf(fmaf(f1.y, ba0.w, bs0.w), 0.f);
        a4 += fmaxf(fmaf(f2.x, ba1.x, bs1.x), 0.f);
        a5 += fmaxf(fmaf(f2.y, ba1.y, bs1.y), 0.f);
        a6 += fmaxf(fmaf(f3.x, ba1.z, bs1.z), 0.f);
        a7 += fmaxf(fmaf(f3.y, ba1.w, bs1.w), 0.f);
    }
    float* dp = &g_aggr[(size_t)n * EMBD + c];
    *(float4*)dp       = make_float4(a0, a1, a2, a3);
    *(float4*)(dp + 4) = make_float4(a4, a5, a6, a7);
}

// ---------------- node layer 1 ----------------
__global__ void __launch_bounds__(256) k_u1(const float* pos, const float* vel, const float* uW1) {
    __shared__ __align__(16) float as_[64][68];
    __shared__ __align__(16) float sw[64][64];
    __shared__ float red[16][64];
    __shared__ float sx[64][4];
    int tid = threadIdx.x;
    int n0 = blockIdx.x * 64;
#pragma unroll
    for (int i = 0; i < 16; i++) { int idx = i * 256 + tid; sw[idx >> 6][idx & 63] = uW1[4096 + idx]; }
    if (tid < 64) {
        int n = n0 + tid;
        if (n < NN) {
            sx[tid][0] = pos[2 * n]; sx[tid][1] = pos[2 * n + 1];
            sx[tid][2] = vel[2 * n]; sx[tid][3] = vel[2 * n + 1];
        } else {
            sx[tid][0] = sx[tid][1] = sx[tid][2] = sx[tid][3] = 0.f;
        }
    }
    {
        int c = tid & 63, l = tid >> 6;
#pragma unroll
        for (int j = 0; j < 16; j++) {
            int r = l + 4 * j; int n = n0 + r;
            as_[r][c] = (n < NN) ? g_aggr[(size_t)n * EMBD + c] : 0.f;
        }
    }
    __syncthreads();
    int tx = tid & 15, ty = tid >> 4;
    int c0 = tx * 4, r0 = ty * 4;
    float acc[4][4];
#pragma unroll
    for (int i = 0; i < 4; i++) {
        int r = r0 + i;
#pragma unroll
        for (int j = 0; j < 4; j++) {
            int c = c0 + j;
            acc[i][j] = g_cbu[c] + sx[r][0] * g_Cu[c] + sx[r][1] * g_Cu[64 + c]
                      + sx[r][2] * g_Cu[128 + c] + sx[r][3] * g_Cu[192 + c];
        }
    }
    tile_gemm(as_, sw, r0, c0, acc);
    float cs[4] = {0, 0, 0, 0}, cq[4] = {0, 0, 0, 0};
#pragma unroll
    for (int i = 0; i < 4; i++) {
        int n = n0 + r0 + i;
        if (n < NN) {
            float4 o; o.x = acc[i][0]; o.y = acc[i][1]; o.z = acc[i][2]; o.w = acc[i][3];
            *(float4*)&g_y3[(size_t)n * EMBD + c0] = o;
#pragma unroll
            for (int j = 0; j < 4; j++) { cs[j] += acc[i][j]; cq[j] += acc[i][j] * acc[i][j]; }
        }
    }
    tile_stats(red, ty, c0, cs, cq, &g_stats[256], &g_stats[320]);
}

// ---------------- node layer 2 ----------------
__global__ void __launch_bounds__(256) k_u2(const float* uW2, const float* ub2) {
    __shared__ __align__(16) float as_[64][68];
    __shared__ __align__(16) float sw[64][64];
    __shared__ float red[16][64];
    int tid = threadIdx.x;
    int n0 = blockIdx.x * 64;
#pragma unroll
    for (int i = 0; i < 16; i++) { int idx = i * 256 + tid; sw[idx >> 6][idx & 63] = uW2[idx]; }
    {
        int c = tid & 63, l = tid >> 6;
        float a3 = g_bn[256 + c], s3 = g_bn[320 + c];
#pragma unroll
        for (int j = 0; j < 16; j++) {
            int r = l + 4 * j; int n = n0 + r;
            as_[r][c] = (n < NN) ? fmaxf(fmaf(g_y3[(size_t)n * EMBD + c], a3, s3), 0.f) : 0.f;
        }
    }
    __syncthreads();
    int tx = tid & 15, ty = tid >> 4;
    int c0 = tx * 4, r0 = ty * 4;
    float acc[4][4];
#pragma unroll
    for (int j = 0; j < 4; j++) {
        float b = ub2[c0 + j];
        acc[0][j] = b; acc[1][j] = b; acc[2][j] = b; acc[3][j] = b;
    }
    tile_gemm(as_, sw, r0, c0, acc);
    float cs[4] = {0, 0, 0, 0}, cq[4] = {0, 0, 0, 0};
#pragma unroll
    for (int i = 0; i < 4; i++) {
        int n = n0 + r0 + i;
        if (n < NN) {
            float4 o; o.x = acc[i][0]; o.y = acc[i][1]; o.z = acc[i][2]; o.w = acc[i][3];
            *(float4*)&g_y4[(size_t)n * EMBD + c0] = o;
#pragma unroll
            for (int j = 0; j < 4; j++) { cs[j] += acc[i][j]; cq[j] += acc[i][j] * acc[i][j]; }
        }
    }
    tile_stats(red, ty, c0, cs, cq, &g_stats[384], &g_stats[448]);
}

// ---------------- head ----------------
__global__ void k_out(const float* Wp, const float* bp, float* out) {
    int w = threadIdx.x >> 5, lane = threadIdx.x & 31;
    int n = blockIdx.x * 8 + w;
    if (n >= NN) return;
    float v0 = g_y4[(size_t)n * EMBD + lane];
    float v1 = g_y4[(size_t)n * EMBD + 32 + lane];
    float u0 = fmaxf(fmaf(v0, g_bn[384 + lane], g_bn[448 + lane]), 0.f);
    float u1 = fmaxf(fmaf(v1, g_bn[384 + 32 + lane], g_bn[448 + 32 + lane]), 0.f);
    float t = u0 * Wp[lane] + u1 * Wp[32 + lane];
#pragma unroll
    for (int o = 16; o; o >>= 1) t += __shfl_down_sync(0xffffffff, t, o);
    if (lane == 0) out[n] = t + bp[0];
}

extern "C" void kernel_launch(void* const* d_in, const int* in_sizes, int n_in,
                              void* d_out, int out_size) {
    const float* pos  = (const float*)d_in[0];
    const float* vel  = (const float*)d_in[1];
    const void*  ei   = d_in[2];
    const float* W_in = (const float*)d_in[3];
    const float* b_in = (const float*)d_in[4];
    const float* mW1  = (const float*)d_in[5];
    const float* mb1  = (const float*)d_in[6];
    const float* mg1  = (const float*)d_in[7];
    const float* mB1  = (const float*)d_in[8];
    const float* mW2  = (const float*)d_in[9];
    const float* mb2  = (const float*)d_in[10];
    const float* mg2  = (const float*)d_in[11];
    const float* mB2  = (const float*)d_in[12];
    const float* uW1  = (const float*)d_in[13];
    const float* ub1  = (const float*)d_in[14];
    const float* ug1  = (const float*)d_in[15];
    const float* uB1  = (const float*)d_in[16];
    const float* uW2  = (const float*)d_in[17];
    const float* ub2  = (const float*)d_in[18];
    const float* ug2  = (const float*)d_in[19];
    const float* uB2  = (const float*)d_in[20];
    const float* Wp   = (const float*)d_in[21];
    const float* bp   = (const float*)d_in[22];
    float* out = (float*)d_out;
    (void)in_sizes; (void)n_in; (void)out_size;

    k_init<<<(NN + 255) / 256, 256>>>((const unsigned int*)ei);
    k_conv<<<(NE + 255) / 256, 256>>>(ei);
    k_scanA<<<SCANB, 256>>>();
    k_scanB<<<1, 128>>>();
    k_scanC<<<SCANB, 1024>>>();
    k_scatter<<<(NE + 255) / 256, 256>>>();
    k_pre<<<3, 256>>>(W_in, b_in, mW1, mb1, uW1, ub1);
    k_pq<<<(NN * EMBD + 255) / 256, 256>>>(pos, vel);
    k_e1<<<512, 256>>>();
    k_bn<<<1, 64>>>(0, (float)NE, mg1, mB1);
    k_e2<<<444, 256>>>(mW2, mb2);
    k_bn<<<1, 64>>>(1, (float)NE, mg2, mB2);
    k_e3<<<(NN * 8 + 255) / 256, 256>>>();
    k_u1<<<(NN + 63) / 64, 256>>>(pos, vel, uW1);
    k_bn<<<1, 64>>>(2, (float)NN, ug1, uB1);
    k_u2<<<(NN + 63) / 64, 256>>>(uW2, ub2);
    k_bn<<<1, 64>>>(3, (float)NN, ug2, uB2);
    k_out<<<(NN + 7) / 8, 256>>>(Wp, bp, out);
}